// round 13
// baseline (speedup 1.0000x reference)
#include <cuda_runtime.h>
#include <cuda_fp16.h>
#include <cstddef>
#include <cstdint>

#define BB   16
#define MID  128
#define OUTC 512
#define HH   112
#define WW   112
#define HW   (HH*WW)      // 12544
#define OH   56
#define OW   56
#define OHW  (OH*OW)      // 3136
#define EPSF 1e-5f

// ---- packed f32x2 helpers ----
#define FMA2(acc, a, b) \
    asm("fma.rn.f32x2 %0, %1, %2, %0;" : "+l"(acc) : "l"(a), "l"(b))
#define PACK2(out, lo, hi) \
    asm("mov.b64 %0, {%1, %2};" : "=l"(out) : "r"(lo), "r"(hi))
#define UNPACK2(lo, hi, v) \
    asm("mov.b64 {%0, %1}, %2;" : "=r"(lo), "=r"(hi) : "l"(v))

// ---- legacy tensor-core mma fp16 (baseline PTX, works on sm_103 non-'a') ----
__device__ __forceinline__ void mma_f16(float* c, const uint32_t* a,
                                        uint32_t b0, uint32_t b1) {
    asm volatile(
        "mma.sync.aligned.m16n8k16.row.col.f32.f16.f16.f32 "
        "{%0,%1,%2,%3}, {%4,%5,%6,%7}, {%8,%9}, {%0,%1,%2,%3};"
        : "+f"(c[0]), "+f"(c[1]), "+f"(c[2]), "+f"(c[3])
        : "r"(a[0]), "r"(a[1]), "r"(a[2]), "r"(a[3]), "r"(b0), "r"(b1));
}

#define LDMX4(r0, r1, r2, r3, addr) \
    asm volatile("ldmatrix.sync.aligned.m8n8.x4.shared.b16 {%0,%1,%2,%3}, [%4];" \
        : "=r"(r0), "=r"(r1), "=r"(r2), "=r"(r3) : "r"(addr))

__device__ __forceinline__ uint32_t smem_u32(const void* p) {
    uint32_t a;
    asm("{ .reg .u64 t; cvta.to.shared.u64 t, %1; cvt.u32.u64 %0, t; }" : "=r"(a) : "l"(p));
    return a;
}

// ---- scratch (static device globals; no allocation; 128B-aligned) ----
__device__ __align__(128) float g_pooled[BB*MID];
__device__ __align__(128) float g_gen[BB*MID*9];
__device__ __align__(128) float g_t[(size_t)BB*MID*HW];
__device__ __align__(128) float g_combined[(size_t)BB*2*MID*HW];   // NCHW fp32 (local half used)
__device__ __align__(128) __half g_bhi[(size_t)BB*114*114*256];    // padded NHWC fp16 hi
__device__ __align__(128) __half g_blo[(size_t)BB*114*114*256];    // padded NHWC fp16 lo
__device__ __align__(128) __half g_wh[(size_t)9*OUTC*256];         // [tap][co][cin] fp16

// ============================================================
// 1) global average pool
// ============================================================
__global__ void pool_kernel(const float* __restrict__ x) {
    int bc = blockIdx.x;
    int b = bc / MID, c = bc % MID;
    const float4* p = (const float4*)(x + ((size_t)(b*2*MID + c))*HW);
    float s = 0.f;
    for (int i = threadIdx.x; i < HW/4; i += 256) {
        float4 v = p[i];
        s += v.x + v.y + v.z + v.w;
    }
    __shared__ float red[256];
    red[threadIdx.x] = s;
    __syncthreads();
    for (int o = 128; o > 0; o >>= 1) {
        if (threadIdx.x < o) red[threadIdx.x] += red[threadIdx.x + o];
        __syncthreads();
    }
    if (threadIdx.x == 0) g_pooled[bc] = red[0] * (1.f/(float)HW);
}

// ============================================================
// 2) kernel-gen
// ============================================================
__global__ void gen_kernel(const float* __restrict__ Wkg) {
    int b = blockIdx.x;
    int o = blockIdx.y * 128 + threadIdx.x;
    __shared__ float ps[MID];
    ps[threadIdx.x] = g_pooled[b*MID + threadIdx.x];
    __syncthreads();
    const float4* wr = (const float4*)(Wkg + (size_t)o*MID);
    float s = 0.f;
    #pragma unroll
    for (int i = 0; i < MID/4; i++) {
        float4 w4 = wr[i];
        s += w4.x*ps[4*i] + w4.y*ps[4*i+1] + w4.z*ps[4*i+2] + w4.w*ps[4*i+3];
    }
    g_gen[b*MID*9 + o] = fmaxf(s, 0.f);
}

// ============================================================
// 3) depthwise 3x3 (dil 1 or 2), half-row per thread
// ============================================================
template<int DIL>
__global__ void dw_kernel(const float* __restrict__ x, int in_chan_off,
                          const float* __restrict__ kper,
                          const float* __restrict__ bias,
                          float* __restrict__ outbuf, int out_nchan) {
    constexpr int P  = DIL;
    constexpr int W2 = WW + 2*P;
    constexpr int H2 = HH + 2*P;
    extern __shared__ float sm[];
    int bc = blockIdx.x;
    int b = bc / MID, c = bc % MID;
    const float* in = x + ((size_t)(b*2*MID) + in_chan_off + c)*HW;
    int tid = threadIdx.x;

    for (int i = tid; i < H2*W2; i += 256) sm[i] = 0.f;
    __syncthreads();
    int r = tid >> 1, c0 = (tid & 1)*56;
    if (tid < 224) {
        const float* ip = in + r*WW + c0;
        float* sp = sm + (r+P)*W2 + c0 + P;
        #pragma unroll 8
        for (int q = 0; q < 56; q++) sp[q] = ip[q];
    }
    __syncthreads();

    float k[9];
    const float* kp = kper ? (kper + c*9) : (g_gen + (b*MID + c)*9);
    #pragma unroll
    for (int t = 0; t < 9; t++) k[t] = kp[t];
    float bv = bias ? bias[c] : 0.f;

    if (tid < 224) {
        float* op = outbuf + ((size_t)b*out_nchan + c)*HW + r*WW + c0;
        const float* base = sm + r*W2 + c0;
        #pragma unroll 4
        for (int q = 0; q < 56; q++) {
            float s = bv;
            #pragma unroll
            for (int kh = 0; kh < 3; kh++)
                #pragma unroll
                for (int kw = 0; kw < 3; kw++)
                    s = fmaf(base[kh*DIL*W2 + kw*DIL + q], k[kh*3+kw], s);
            op[q] = s;
        }
    }
}

// ============================================================
// 4) 1x1 conv + bias + BN + ReLU (f32x2); writes NHWC fp16 hi/lo
//    directly into g_bhi/g_blo channels [128..255]
// ============================================================
__global__ void pw_kernel(const float* __restrict__ wpw, const float* __restrict__ bpw,
                          const float* __restrict__ bn_g, const float* __restrict__ bn_b,
                          const float* __restrict__ bn_m, const float* __restrict__ bn_v) {
    __shared__ __align__(16) float wS[16*132];
    __shared__ __align__(16) float tS[16*132];
    int b  = blockIdx.y;
    int p0 = blockIdx.x * 128;
    int tid = threadIdx.x;
    int ty = tid >> 4, tx = tid & 15;
    unsigned long long acc[8][4];
    #pragma unroll
    for (int i = 0; i < 8; i++)
        #pragma unroll
        for (int j = 0; j < 4; j++) acc[i][j] = 0ULL;
    const float* tbase = g_t + (size_t)b*MID*HW;

    for (int kc = 0; kc < 8; kc++) {
        __syncthreads();
        for (int idx = tid; idx < 2048; idx += 256) {
            int k = idx & 15, co = idx >> 4;
            wS[k*132 + co] = wpw[co*MID + kc*16 + k];
        }
        for (int idx = tid; idx < 2048; idx += 256) {
            int k = idx >> 7, px = idx & 127;
            tS[k*132 + px] = tbase[(kc*16 + k)*HW + p0 + px];
        }
        __syncthreads();
        #pragma unroll
        for (int k = 0; k < 16; k++) {
            float4 a0 = *(const float4*)&wS[k*132 + ty*8];
            float4 a1 = *(const float4*)&wS[k*132 + ty*8 + 4];
            float a[8] = {a0.x,a0.y,a0.z,a0.w,a1.x,a1.y,a1.z,a1.w};
            unsigned long long ad[8];
            #pragma unroll
            for (int i = 0; i < 8; i++) {
                unsigned int ab = __float_as_uint(a[i]);
                PACK2(ad[i], ab, ab);
            }
            const ulonglong2* bp = (const ulonglong2*)&tS[k*132 + tx*8];
            ulonglong2 b01 = bp[0];
            ulonglong2 b23 = bp[1];
            unsigned long long bv[4] = {b01.x, b01.y, b23.x, b23.y};
            #pragma unroll
            for (int i = 0; i < 8; i++)
                #pragma unroll
                for (int j = 0; j < 4; j++)
                    FMA2(acc[i][j], ad[i], bv[j]);
        }
    }
    // BN+ReLU, then hi/lo fp16 split, NHWC scatter (8 co contiguous)
    float inv[8], sh[8];
    #pragma unroll
    for (int i = 0; i < 8; i++) {
        int co = ty*8 + i;
        inv[i] = bn_g[co] * rsqrtf(bn_v[co] + EPSF);
        sh[i]  = bn_b[co] - bn_m[co]*inv[i] + bpw[co]*inv[i];
    }
    #pragma unroll
    for (int jj = 0; jj < 8; jj++) {
        int px = p0 + tx*8 + jj;
        int h = px / WW, wq = px % WW;
        size_t base = (((size_t)b*114 + h + 1)*114 + wq + 1)*256 + MID + ty*8;
        __half hi8[8], lo8[8];
        #pragma unroll
        for (int i = 0; i < 8; i++) {
            unsigned int lo, hi;
            UNPACK2(lo, hi, acc[i][jj >> 1]);
            float v = fmaxf(fmaf(__uint_as_float((jj & 1) ? hi : lo), inv[i], sh[i]), 0.f);
            __half hv = __float2half_rn(v);
            hi8[i] = hv;
            lo8[i] = __float2half_rn(v - __half2float(hv));
        }
        *(uint4*)(g_bhi + base) = *(const uint4*)hi8;
        *(uint4*)(g_blo + base) = *(const uint4*)lo8;
    }
}

// ============================================================
// 5a) weight repack: dsw[co][cin][tap] -> [tap][co][cin] fp16
// ============================================================
__global__ void repack_kernel(const float* __restrict__ dsw) {
    int co = blockIdx.x, cin = threadIdx.x;
    const float* src = dsw + ((size_t)co*256 + cin)*9;
    #pragma unroll
    for (int t = 0; t < 9; t++)
        g_wh[((size_t)t*OUTC + co)*256 + cin] = __float2half_rn(src[t]);
}

// ============================================================
// 5b) border zero for padded NHWC fp16 buffers
// ============================================================
__global__ void border_kernel() {
    size_t base = (size_t)blockIdx.x * 114*114*256;
    int tid = threadIdx.x;
    __half z = __float2half_rn(0.f);
    for (int idx = tid; idx < 114*256; idx += 256) {
        g_bhi[base + idx] = z;  g_blo[base + idx] = z;
        g_bhi[base + (size_t)113*114*256 + idx] = z;
        g_blo[base + (size_t)113*114*256 + idx] = z;
    }
    for (int idx = tid; idx < 112*256; idx += 256) {
        int h = idx >> 8, c = idx & 255;
        size_t i0 = base + ((size_t)(h+1)*114)*256 + c;
        size_t i1 = base + ((size_t)(h+1)*114 + 113)*256 + c;
        g_bhi[i0] = z; g_blo[i0] = z;
        g_bhi[i1] = z; g_blo[i1] = z;
    }
}

// ============================================================
// 5c) transpose LOCAL half: NCHW fp32 -> padded NHWC fp16 hi/lo
// ============================================================
__global__ void transpose_kernel() {
    __shared__ float t[64][113];
    int h = blockIdx.x, b = blockIdx.y;
    int tid = threadIdx.x;
    for (int c0 = 0; c0 < 128; c0 += 64) {
        for (int idx = tid; idx < 64*112; idx += 256) {
            int c = idx / 112, w = idx % 112;
            t[c][w] = g_combined[((size_t)(b*256 + c0 + c))*HW + h*WW + w];
        }
        __syncthreads();
        size_t dbase = (((size_t)b*114 + h + 1)*114 + 1)*256 + c0;
        for (int idx = tid; idx < 112*64; idx += 256) {
            int w = idx >> 6, c = idx & 63;
            float v = t[c][w];
            __half hi = __float2half_rn(v);
            float r = v - __half2float(hi);
            g_bhi[dbase + (size_t)w*256 + c] = hi;
            g_blo[dbase + (size_t)w*256 + c] = __float2half_rn(r);
        }
        __syncthreads();
    }
}

// ============================================================
// 6) downsample: mma.sync fp16 2-term implicit GEMM
//    K=64 per stage (36 stages), register-prefetch double buffer,
//    ldmatrix fragments; rows 128B data + 16B pad (144B stride)
//    CTA: 128 co x 128 px; 8 warps, warp tile 64x32
// ============================================================
#define RS_B     144                     // row stride bytes
#define RS_W     36                      // row stride words
#define OPB      (128*RS_B)              // 18432 B per operand
#define OPW      (OPB/4)                 // 4608 words
#define STG_W    (3*OPW)                 // 13824 words per stage
#define DS_SMEM  (2*3*OPB)               // 110592 B
__global__ void __launch_bounds__(256, 2) ds_mma_kernel(
    const float* __restrict__ dsb,
    const float* __restrict__ bn_g, const float* __restrict__ bn_b,
    const float* __restrict__ bn_m, const float* __restrict__ bn_v,
    float* __restrict__ out) {
    extern __shared__ __align__(16) uint32_t smw[];   // 2*13824 words
    uint32_t smemB = smem_u32(smw);
    int tid  = threadIdx.x;
    int lane = tid & 31, w = tid >> 5;
    int wm = w & 1, wn = w >> 1;
    int coB = blockIdx.x * 128;
    int p0  = blockIdx.y * 128;

    // staging: thread -> (row r, half hf); each half = 64B = 4x16B per operand
    int r  = tid >> 1, hf = tid & 1;
    size_t aBase = (size_t)(coB + r)*256 + hf*32;
    size_t bBase;
    {
        int pg = p0 + r;
        int bimg = pg / OHW, lpx = pg % OHW;
        int ohh = lpx / OW, oww = lpx % OW;
        bBase = ((size_t)(bimg*114 + 2*ohh)*114 + 2*oww)*256 + hf*32;
    }
    uint32_t sA = (uint32_t)(r*RS_W + hf*16);     // word offset

    // ldmatrix lane addressing (byte offsets within operand)
    uint32_t aLm = (uint32_t)((wm*64 + (lane & 15))*RS_B + (lane >> 4)*16);
    uint32_t bLm = (uint32_t)((wn*32 + (lane & 7) + ((lane >> 4) & 1)*8)*RS_B
                              + ((lane >> 3) & 1)*16);

    float acc[4][4][4];
    #pragma unroll
    for (int i = 0; i < 4; i++)
        #pragma unroll
        for (int j = 0; j < 4; j++)
            #pragma unroll
            for (int e = 0; e < 4; e++) acc[i][j][e] = 0.f;

    float4 rA[4], rH[4], rL[4];
    // prefetch stage 0 (tap 0, cc2 0)
    {
        const float4* ap = (const float4*)(g_wh + aBase);
        const float4* hp = (const float4*)(g_bhi + bBase);
        const float4* lp = (const float4*)(g_blo + bBase);
        #pragma unroll
        for (int v = 0; v < 4; v++) { rA[v] = ap[v]; rH[v] = hp[v]; rL[v] = lp[v]; }
    }

    for (int st = 0; st < 36; st++) {
        uint32_t sbW = (uint32_t)(st & 1) * STG_W;
        {   // store prefetched regs into this stage's buffer
            float4* ad = (float4*)(smw + sbW + sA);
            float4* hd = (float4*)(smw + sbW + OPW + sA);
            float4* ld = (float4*)(smw + sbW + 2*OPW + sA);
            #pragma unroll
            for (int v = 0; v < 4; v++) { ad[v] = rA[v]; hd[v] = rH[v]; ld[v] = rL[v]; }
        }
        __syncthreads();
        if (st < 35) {     // prefetch next stage (in flight during compute)
            int sn = st + 1;
            int tap = sn >> 2, cc2 = sn & 3;
            size_t ao = aBase + (size_t)tap*(OUTC*256) + cc2*64;
            size_t bo = bBase + (size_t)((tap/3)*114 + tap%3)*256 + cc2*64;
            const float4* ap = (const float4*)(g_wh + ao);
            const float4* hp = (const float4*)(g_bhi + bo);
            const float4* lp = (const float4*)(g_blo + bo);
            #pragma unroll
            for (int v = 0; v < 4; v++) { rA[v] = ap[v]; rH[v] = hp[v]; rL[v] = lp[v]; }
        }
        // compute from buffer via ldmatrix (4 k16 sub-steps)
        uint32_t bufA  = smemB + sbW*4;
        uint32_t bufBh = bufA + OPB;
        uint32_t bufBl = bufA + 2*OPB;
        #pragma unroll
        for (int s2 = 0; s2 < 4; s2++) {
            uint32_t bh[8], bl[8];
            LDMX4(bh[0], bh[1], bh[2], bh[3], bufBh + bLm + s2*32);
            LDMX4(bh[4], bh[5], bh[6], bh[7], bufBh + bLm + 16*RS_B + s2*32);
            LDMX4(bl[0], bl[1], bl[2], bl[3], bufBl + bLm + s2*32);
            LDMX4(bl[4], bl[5], bl[6], bl[7], bufBl + bLm + 16*RS_B + s2*32);
            #pragma unroll
            for (int i = 0; i < 4; i++) {
                uint32_t a[4];
                LDMX4(a[0], a[1], a[2], a[3], bufA + aLm + i*16*RS_B + s2*32);
                #pragma unroll
                for (int j = 0; j < 4; j++) {
                    int p2 = (j >> 1)*4 + (j & 1)*2;
                    mma_f16(acc[i][j], a, bh[p2], bh[p2+1]);   // hi * hi
                    mma_f16(acc[i][j], a, bl[p2], bl[p2+1]);   // hi * lo
                }
            }
        }
    }

    // epilogue: BN + ReLU, scatter to NCHW out
    int g  = lane >> 2, tig = lane & 3;
    #pragma unroll
    for (int i = 0; i < 4; i++) {
        int coA = coB + wm*64 + i*16 + g;
        int coC = coA + 8;
        float invA = bn_g[coA] * rsqrtf(bn_v[coA] + EPSF);
        float shA  = bn_b[coA] - bn_m[coA]*invA + dsb[coA]*invA;
        float invC = bn_g[coC] * rsqrtf(bn_v[coC] + EPSF);
        float shC  = bn_b[coC] - bn_m[coC]*invC + dsb[coC]*invC;
        #pragma unroll
        for (int j = 0; j < 4; j++) {
            int n0 = p0 + wn*32 + j*8 + 2*tig;
            #pragma unroll
            for (int e = 0; e < 2; e++) {
                int pgx = n0 + e;
                int b = pgx / OHW, l = pgx % OHW;
                out[((size_t)(b*OUTC + coA))*OHW + l] =
                    fmaxf(fmaf(acc[i][j][e], invA, shA), 0.f);
                out[((size_t)(b*OUTC + coC))*OHW + l] =
                    fmaxf(fmaf(acc[i][j][2+e], invC, shC), 0.f);
            }
        }
    }
}

// ============================================================
extern "C" void kernel_launch(void* const* d_in, const int* in_sizes, int n_in,
                              void* d_out, int out_size) {
    const float* x     = (const float*)d_in[0];
    const float* Wkg   = (const float*)d_in[1];
    const float* gdw_w = (const float*)d_in[2];
    const float* gdw_b = (const float*)d_in[3];
    const float* gpw_w = (const float*)d_in[4];
    const float* gpw_b = (const float*)d_in[5];
    const float* bn1_g = (const float*)d_in[6];
    const float* bn1_b = (const float*)d_in[7];
    const float* bn1_m = (const float*)d_in[8];
    const float* bn1_v = (const float*)d_in[9];
    const float* ds_w  = (const float*)d_in[10];
    const float* ds_b  = (const float*)d_in[11];
    const float* bn2_g = (const float*)d_in[12];
    const float* bn2_b = (const float*)d_in[13];
    const float* bn2_m = (const float*)d_in[14];
    const float* bn2_v = (const float*)d_in[15];
    float* out = (float*)d_out;

    const int smem1 = (HH+2)*(WW+2)*sizeof(float);
    const int smem2 = (HH+4)*(WW+4)*sizeof(float);
    cudaFuncSetAttribute(dw_kernel<1>, cudaFuncAttributeMaxDynamicSharedMemorySize, smem1);
    cudaFuncSetAttribute(dw_kernel<2>, cudaFuncAttributeMaxDynamicSharedMemorySize, smem2);
    cudaFuncSetAttribute(ds_mma_kernel, cudaFuncAttributeMaxDynamicSharedMemorySize, DS_SMEM);

    float* t_ptr;    cudaGetSymbolAddress((void**)&t_ptr, g_t);
    float* comb_ptr; cudaGetSymbolAddress((void**)&comb_ptr, g_combined);

    repack_kernel<<<OUTC, 256>>>(ds_w);
    border_kernel<<<BB, 256>>>();
    pool_kernel<<<BB*MID, 256>>>(x);
    gen_kernel<<<dim3(BB, 9), 128>>>(Wkg);
    dw_kernel<1><<<BB*MID, 256, smem1>>>(x, 0, nullptr, nullptr, comb_ptr, 2*MID);
    dw_kernel<2><<<BB*MID, 256, smem2>>>(x, MID, gdw_w, gdw_b, t_ptr, MID);
    pw_kernel<<<dim3(HW/128, BB), 256>>>(gpw_w, gpw_b, bn1_g, bn1_b, bn1_m, bn1_v);
    transpose_kernel<<<dim3(HH, BB), 256>>>();
    ds_mma_kernel<<<dim3(4, (BB*OHW)/128), 256, DS_SMEM>>>(
        ds_b, bn2_g, bn2_b, bn2_m, bn2_v, out);
}

// round 14
// speedup vs baseline: 1.3079x; 1.3079x over previous
#include <cuda_runtime.h>
#include <cuda_fp16.h>
#include <cstddef>
#include <cstdint>

#define BB   16
#define MID  128
#define OUTC 512
#define HH   112
#define WW   112
#define HW   (HH*WW)      // 12544
#define OH   56
#define OW   56
#define OHW  (OH*OW)      // 3136
#define EPSF 1e-5f

// ---- packed f32x2 helpers ----
#define FMA2(acc, a, b) \
    asm("fma.rn.f32x2 %0, %1, %2, %0;" : "+l"(acc) : "l"(a), "l"(b))
#define PACK2(out, lo, hi) \
    asm("mov.b64 %0, {%1, %2};" : "=l"(out) : "r"(lo), "r"(hi))
#define UNPACK2(lo, hi, v) \
    asm("mov.b64 {%0, %1}, %2;" : "=r"(lo), "=r"(hi) : "l"(v))

// ---- legacy tensor-core mma fp16 (baseline PTX, works on sm_103 non-'a') ----
__device__ __forceinline__ void mma_f16(float* c, const uint32_t* a,
                                        uint32_t b0, uint32_t b1) {
    asm volatile(
        "mma.sync.aligned.m16n8k16.row.col.f32.f16.f16.f32 "
        "{%0,%1,%2,%3}, {%4,%5,%6,%7}, {%8,%9}, {%0,%1,%2,%3};"
        : "+f"(c[0]), "+f"(c[1]), "+f"(c[2]), "+f"(c[3])
        : "r"(a[0]), "r"(a[1]), "r"(a[2]), "r"(a[3]), "r"(b0), "r"(b1));
}

#define LDMX4(r0, r1, r2, r3, addr) \
    asm volatile("ldmatrix.sync.aligned.m8n8.x4.shared.b16 {%0,%1,%2,%3}, [%4];" \
        : "=r"(r0), "=r"(r1), "=r"(r2), "=r"(r3) : "r"(addr))

__device__ __forceinline__ uint32_t smem_u32(const void* p) {
    uint32_t a;
    asm("{ .reg .u64 t; cvta.to.shared.u64 t, %1; cvt.u32.u64 %0, t; }" : "=r"(a) : "l"(p));
    return a;
}

// ---- scratch (static device globals; no allocation; 128B-aligned) ----
__device__ __align__(128) float g_pooled[BB*MID];
__device__ __align__(128) float g_gen[BB*MID*9];
__device__ __align__(128) float g_t[(size_t)BB*MID*HW];
__device__ __align__(128) float g_combined[(size_t)BB*2*MID*HW];   // NCHW fp32 (local half used)
__device__ __align__(128) __half g_bhi[(size_t)BB*114*114*256];    // padded NHWC fp16 hi
__device__ __align__(128) __half g_blo[(size_t)BB*114*114*256];    // padded NHWC fp16 lo
__device__ __align__(128) __half g_wh[(size_t)9*OUTC*256];         // [tap][co][cin] fp16

// ============================================================
// 1) global average pool
// ============================================================
__global__ void pool_kernel(const float* __restrict__ x) {
    int bc = blockIdx.x;
    int b = bc / MID, c = bc % MID;
    const float4* p = (const float4*)(x + ((size_t)(b*2*MID + c))*HW);
    float s = 0.f;
    for (int i = threadIdx.x; i < HW/4; i += 256) {
        float4 v = p[i];
        s += v.x + v.y + v.z + v.w;
    }
    __shared__ float red[256];
    red[threadIdx.x] = s;
    __syncthreads();
    for (int o = 128; o > 0; o >>= 1) {
        if (threadIdx.x < o) red[threadIdx.x] += red[threadIdx.x + o];
        __syncthreads();
    }
    if (threadIdx.x == 0) g_pooled[bc] = red[0] * (1.f/(float)HW);
}

// ============================================================
// 2) kernel-gen
// ============================================================
__global__ void gen_kernel(const float* __restrict__ Wkg) {
    int b = blockIdx.x;
    int o = blockIdx.y * 128 + threadIdx.x;
    __shared__ float ps[MID];
    ps[threadIdx.x] = g_pooled[b*MID + threadIdx.x];
    __syncthreads();
    const float4* wr = (const float4*)(Wkg + (size_t)o*MID);
    float s = 0.f;
    #pragma unroll
    for (int i = 0; i < MID/4; i++) {
        float4 w4 = wr[i];
        s += w4.x*ps[4*i] + w4.y*ps[4*i+1] + w4.z*ps[4*i+2] + w4.w*ps[4*i+3];
    }
    g_gen[b*MID*9 + o] = fmaxf(s, 0.f);
}

// ============================================================
// 3) depthwise 3x3 (dil 1 or 2), HALF-PLANE per CTA (56 rows + halo)
//    grid: (BB*MID, 2); smem ~27 KB -> 8 CTAs/SM
// ============================================================
template<int DIL>
__global__ void dw_kernel(const float* __restrict__ x, int in_chan_off,
                          const float* __restrict__ kper,
                          const float* __restrict__ bias,
                          float* __restrict__ outbuf, int out_nchan) {
    constexpr int P  = DIL;
    constexpr int W2 = WW + 2*P;
    constexpr int RH = 56;            // output rows per CTA
    constexpr int H2 = RH + 2*P;
    extern __shared__ float sm[];
    int bc = blockIdx.x;
    int r0 = blockIdx.y * RH;         // first output row of this CTA
    int b = bc / MID, c = bc % MID;
    const float* in = x + ((size_t)(b*2*MID) + in_chan_off + c)*HW;
    int tid = threadIdx.x;

    // stage rows [r0-P, r0+RH+P) with zero halo
    for (int i = tid; i < H2*W2; i += 256) {
        int lr = i / W2, lc = i % W2;
        int gr = r0 - P + lr, gc = lc - P;
        float v = 0.f;
        if ((unsigned)gr < HH && (unsigned)gc < WW) v = in[gr*WW + gc];
        sm[i] = v;
    }
    __syncthreads();

    float k[9];
    const float* kp = kper ? (kper + c*9) : (g_gen + (b*MID + c)*9);
    #pragma unroll
    for (int t = 0; t < 9; t++) k[t] = kp[t];
    float bv = bias ? bias[c] : 0.f;

    // 224 threads: quarter-row each (28 px), rows r0..r0+55
    if (tid < 224) {
        int lr = tid >> 2, c0 = (tid & 3)*28;
        float* op = outbuf + ((size_t)b*out_nchan + c)*HW + (r0 + lr)*WW + c0;
        const float* base = sm + lr*W2 + c0;
        #pragma unroll 4
        for (int q = 0; q < 28; q++) {
            float s = bv;
            #pragma unroll
            for (int kh = 0; kh < 3; kh++)
                #pragma unroll
                for (int kw = 0; kw < 3; kw++)
                    s = fmaf(base[kh*DIL*W2 + kw*DIL + q], k[kh*3+kw], s);
            op[q] = s;
        }
    }
}

// ============================================================
// 4) 1x1 conv + bias + BN + ReLU (f32x2); writes NHWC fp16 hi/lo
//    directly into g_bhi/g_blo channels [128..255]
// ============================================================
__global__ void pw_kernel(const float* __restrict__ wpw, const float* __restrict__ bpw,
                          const float* __restrict__ bn_g, const float* __restrict__ bn_b,
                          const float* __restrict__ bn_m, const float* __restrict__ bn_v) {
    __shared__ __align__(16) float wS[16*132];
    __shared__ __align__(16) float tS[16*132];
    int b  = blockIdx.y;
    int p0 = blockIdx.x * 128;
    int tid = threadIdx.x;
    int ty = tid >> 4, tx = tid & 15;
    unsigned long long acc[8][4];
    #pragma unroll
    for (int i = 0; i < 8; i++)
        #pragma unroll
        for (int j = 0; j < 4; j++) acc[i][j] = 0ULL;
    const float* tbase = g_t + (size_t)b*MID*HW;

    for (int kc = 0; kc < 8; kc++) {
        __syncthreads();
        for (int idx = tid; idx < 2048; idx += 256) {
            int k = idx & 15, co = idx >> 4;
            wS[k*132 + co] = wpw[co*MID + kc*16 + k];
        }
        for (int idx = tid; idx < 2048; idx += 256) {
            int k = idx >> 7, px = idx & 127;
            tS[k*132 + px] = tbase[(kc*16 + k)*HW + p0 + px];
        }
        __syncthreads();
        #pragma unroll
        for (int k = 0; k < 16; k++) {
            float4 a0 = *(const float4*)&wS[k*132 + ty*8];
            float4 a1 = *(const float4*)&wS[k*132 + ty*8 + 4];
            float a[8] = {a0.x,a0.y,a0.z,a0.w,a1.x,a1.y,a1.z,a1.w};
            unsigned long long ad[8];
            #pragma unroll
            for (int i = 0; i < 8; i++) {
                unsigned int ab = __float_as_uint(a[i]);
                PACK2(ad[i], ab, ab);
            }
            const ulonglong2* bp = (const ulonglong2*)&tS[k*132 + tx*8];
            ulonglong2 b01 = bp[0];
            ulonglong2 b23 = bp[1];
            unsigned long long bv[4] = {b01.x, b01.y, b23.x, b23.y};
            #pragma unroll
            for (int i = 0; i < 8; i++)
                #pragma unroll
                for (int j = 0; j < 4; j++)
                    FMA2(acc[i][j], ad[i], bv[j]);
        }
    }
    // BN+ReLU, then hi/lo fp16 split, NHWC scatter (8 co contiguous)
    float inv[8], sh[8];
    #pragma unroll
    for (int i = 0; i < 8; i++) {
        int co = ty*8 + i;
        inv[i] = bn_g[co] * rsqrtf(bn_v[co] + EPSF);
        sh[i]  = bn_b[co] - bn_m[co]*inv[i] + bpw[co]*inv[i];
    }
    #pragma unroll
    for (int jj = 0; jj < 8; jj++) {
        int px = p0 + tx*8 + jj;
        int h = px / WW, wq = px % WW;
        size_t base = (((size_t)b*114 + h + 1)*114 + wq + 1)*256 + MID + ty*8;
        __half hi8[8], lo8[8];
        #pragma unroll
        for (int i = 0; i < 8; i++) {
            unsigned int lo, hi;
            UNPACK2(lo, hi, acc[i][jj >> 1]);
            float v = fmaxf(fmaf(__uint_as_float((jj & 1) ? hi : lo), inv[i], sh[i]), 0.f);
            __half hv = __float2half_rn(v);
            hi8[i] = hv;
            lo8[i] = __float2half_rn(v - __half2float(hv));
        }
        *(uint4*)(g_bhi + base) = *(const uint4*)hi8;
        *(uint4*)(g_blo + base) = *(const uint4*)lo8;
    }
}

// ============================================================
// 5a) weight repack: dsw[co][cin][tap] -> [tap][co][cin] fp16
// ============================================================
__global__ void repack_kernel(const float* __restrict__ dsw) {
    int co = blockIdx.x, cin = threadIdx.x;
    const float* src = dsw + ((size_t)co*256 + cin)*9;
    #pragma unroll
    for (int t = 0; t < 9; t++)
        g_wh[((size_t)t*OUTC + co)*256 + cin] = __float2half_rn(src[t]);
}

// ============================================================
// 5b) border zero for padded NHWC fp16 buffers
// ============================================================
__global__ void border_kernel() {
    size_t base = (size_t)blockIdx.x * 114*114*256;
    int tid = threadIdx.x;
    __half z = __float2half_rn(0.f);
    for (int idx = tid; idx < 114*256; idx += 256) {
        g_bhi[base + idx] = z;  g_blo[base + idx] = z;
        g_bhi[base + (size_t)113*114*256 + idx] = z;
        g_blo[base + (size_t)113*114*256 + idx] = z;
    }
    for (int idx = tid; idx < 112*256; idx += 256) {
        int h = idx >> 8, c = idx & 255;
        size_t i0 = base + ((size_t)(h+1)*114)*256 + c;
        size_t i1 = base + ((size_t)(h+1)*114 + 113)*256 + c;
        g_bhi[i0] = z; g_blo[i0] = z;
        g_bhi[i1] = z; g_blo[i1] = z;
    }
}

// ============================================================
// 5c) transpose LOCAL half: NCHW fp32 -> padded NHWC fp16 hi/lo
// ============================================================
__global__ void transpose_kernel() {
    __shared__ float t[64][113];
    int h = blockIdx.x, b = blockIdx.y;
    int tid = threadIdx.x;
    for (int c0 = 0; c0 < 128; c0 += 64) {
        for (int idx = tid; idx < 64*112; idx += 256) {
            int c = idx / 112, w = idx % 112;
            t[c][w] = g_combined[((size_t)(b*256 + c0 + c))*HW + h*WW + w];
        }
        __syncthreads();
        size_t dbase = (((size_t)b*114 + h + 1)*114 + 1)*256 + c0;
        for (int idx = tid; idx < 112*64; idx += 256) {
            int w = idx >> 6, c = idx & 63;
            float v = t[c][w];
            __half hi = __float2half_rn(v);
            float r = v - __half2float(hi);
            g_bhi[dbase + (size_t)w*256 + c] = hi;
            g_blo[dbase + (size_t)w*256 + c] = __float2half_rn(r);
        }
        __syncthreads();
    }
}

// ============================================================
// 6) downsample: mma.sync fp16 2-term implicit GEMM (R12-frozen)
//    register-prefetch double buffer + ldmatrix fragments
//    CTA: 128 co x 128 px; 8 warps, warp tile 64x32
//    smem per stage: Ahi / Bhi / Blo, 128 rows x 80B each
// ============================================================
#define STG_W   7680                     // words per stage (3 * 2560)
#define DS_SMEM (2*STG_W*4)              // 61440 B
__global__ void __launch_bounds__(256, 2) ds_mma_kernel(
    const float* __restrict__ dsb,
    const float* __restrict__ bn_g, const float* __restrict__ bn_b,
    const float* __restrict__ bn_m, const float* __restrict__ bn_v,
    float* __restrict__ out) {
    extern __shared__ __align__(16) uint32_t smw[];   // 2*7680 words
    uint32_t smemB = smem_u32(smw);
    int tid  = threadIdx.x;
    int lane = tid & 31, w = tid >> 5;
    int wm = w & 1, wn = w >> 1;
    int coB = blockIdx.x * 128;
    int p0  = blockIdx.y * 128;

    // staging: every thread loads 32B half-rows of Ahi, Bhi, Blo for row r
    int r  = tid >> 1, hf = tid & 1;
    size_t aBase = (size_t)(coB + r)*256 + hf*16;
    size_t bBase;
    {
        int pg = p0 + r;
        int bimg = pg / OHW, lpx = pg % OHW;
        int ohh = lpx / OW, oww = lpx % OW;
        bBase = ((size_t)(bimg*114 + 2*ohh)*114 + 2*oww)*256 + hf*16;
    }
    uint32_t sA = (uint32_t)(r*20 + hf*8);

    // ldmatrix lane addressing (byte offsets within operand; validated)
    uint32_t aLm = (uint32_t)((wm*64 + (lane & 15))*80 + (lane >> 4)*16);
    uint32_t bLm = (uint32_t)((wn*32 + (lane & 7) + ((lane >> 4) & 1)*8)*80
                              + ((lane >> 3) & 1)*16);

    float acc[4][4][4];
    #pragma unroll
    for (int i = 0; i < 4; i++)
        #pragma unroll
        for (int j = 0; j < 4; j++)
            #pragma unroll
            for (int e = 0; e < 4; e++) acc[i][j][e] = 0.f;

    float4 rA0, rA1, rH0, rH1, rL0, rL1;
    // prefetch stage 0
    {
        const float4* ap = (const float4*)(g_wh + aBase);
        rA0 = ap[0]; rA1 = ap[1];
        const float4* hp = (const float4*)(g_bhi + bBase);
        rH0 = hp[0]; rH1 = hp[1];
        const float4* lp = (const float4*)(g_blo + bBase);
        rL0 = lp[0]; rL1 = lp[1];
    }

    for (int st = 0; st < 72; st++) {
        uint32_t sbW = (uint32_t)(st & 1) * STG_W;
        {   // store prefetched regs into this stage's buffer
            float4* ad = (float4*)(smw + sbW + sA);
            ad[0] = rA0; ad[1] = rA1;
            float4* hd = (float4*)(smw + sbW + 2560 + sA);
            hd[0] = rH0; hd[1] = rH1;
            float4* ld = (float4*)(smw + sbW + 5120 + sA);
            ld[0] = rL0; ld[1] = rL1;
        }
        __syncthreads();
        if (st < 71) {     // prefetch next stage (in flight during compute)
            int sn = st + 1;
            int tap = sn >> 3, cc = sn & 7;
            size_t ao = aBase + (size_t)tap*(OUTC*256) + cc*32;
            size_t bo = bBase + (size_t)((tap/3)*114 + tap%3)*256 + cc*32;
            const float4* ap = (const float4*)(g_wh + ao);
            rA0 = ap[0]; rA1 = ap[1];
            const float4* hp = (const float4*)(g_bhi + bo);
            rH0 = hp[0]; rH1 = hp[1];
            const float4* lp = (const float4*)(g_blo + bo);
            rL0 = lp[0]; rL1 = lp[1];
        }
        // compute from buffer via ldmatrix
        uint32_t bufA  = smemB + sbW*4;
        uint32_t bufBh = bufA + 10240;
        uint32_t bufBl = bufA + 20480;
        #pragma unroll
        for (int s2 = 0; s2 < 2; s2++) {
            uint32_t bh[8], bl[8];
            LDMX4(bh[0], bh[1], bh[2], bh[3], bufBh + bLm + s2*32);
            LDMX4(bh[4], bh[5], bh[6], bh[7], bufBh + bLm + 1280 + s2*32);
            LDMX4(bl[0], bl[1], bl[2], bl[3], bufBl + bLm + s2*32);
            LDMX4(bl[4], bl[5], bl[6], bl[7], bufBl + bLm + 1280 + s2*32);
            #pragma unroll
            for (int i = 0; i < 4; i++) {
                uint32_t a[4];
                LDMX4(a[0], a[1], a[2], a[3], bufA + aLm + i*1280 + s2*32);
                #pragma unroll
                for (int j = 0; j < 4; j++) {
                    int p2 = (j >> 1)*4 + (j & 1)*2;
                    mma_f16(acc[i][j], a, bh[p2], bh[p2+1]);   // hi * hi
                    mma_f16(acc[i][j], a, bl[p2], bl[p2+1]);   // hi * lo
                }
            }
        }
    }

    // epilogue: BN + ReLU, scatter to NCHW out
    int g  = lane >> 2, tig = lane & 3;
    #pragma unroll
    for (int i = 0; i < 4; i++) {
        int coA = coB + wm*64 + i*16 + g;
        int coC = coA + 8;
        float invA = bn_g[coA] * rsqrtf(bn_v[coA] + EPSF);
        float shA  = bn_b[coA] - bn_m[coA]*invA + dsb[coA]*invA;
        float invC = bn_g[coC] * rsqrtf(bn_v[coC] + EPSF);
        float shC  = bn_b[coC] - bn_m[coC]*invC + dsb[coC]*invC;
        #pragma unroll
        for (int j = 0; j < 4; j++) {
            int n0 = p0 + wn*32 + j*8 + 2*tig;
            #pragma unroll
            for (int e = 0; e < 2; e++) {
                int pgx = n0 + e;
                int b = pgx / OHW, l = pgx % OHW;
                out[((size_t)(b*OUTC + coA))*OHW + l] =
                    fmaxf(fmaf(acc[i][j][e], invA, shA), 0.f);
                out[((size_t)(b*OUTC + coC))*OHW + l] =
                    fmaxf(fmaf(acc[i][j][2+e], invC, shC), 0.f);
            }
        }
    }
}

// ============================================================
extern "C" void kernel_launch(void* const* d_in, const int* in_sizes, int n_in,
                              void* d_out, int out_size) {
    const float* x     = (const float*)d_in[0];
    const float* Wkg   = (const float*)d_in[1];
    const float* gdw_w = (const float*)d_in[2];
    const float* gdw_b = (const float*)d_in[3];
    const float* gpw_w = (const float*)d_in[4];
    const float* gpw_b = (const float*)d_in[5];
    const float* bn1_g = (const float*)d_in[6];
    const float* bn1_b = (const float*)d_in[7];
    const float* bn1_m = (const float*)d_in[8];
    const float* bn1_v = (const float*)d_in[9];
    const float* ds_w  = (const float*)d_in[10];
    const float* ds_b  = (const float*)d_in[11];
    const float* bn2_g = (const float*)d_in[12];
    const float* bn2_b = (const float*)d_in[13];
    const float* bn2_m = (const float*)d_in[14];
    const float* bn2_v = (const float*)d_in[15];
    float* out = (float*)d_out;

    const int smem1 = (56+2)*(WW+2)*sizeof(float);    // 26448 B
    const int smem2 = (56+4)*(WW+4)*sizeof(float);    // 27840 B
    cudaFuncSetAttribute(dw_kernel<1>, cudaFuncAttributeMaxDynamicSharedMemorySize, smem1);
    cudaFuncSetAttribute(dw_kernel<2>, cudaFuncAttributeMaxDynamicSharedMemorySize, smem2);
    cudaFuncSetAttribute(ds_mma_kernel, cudaFuncAttributeMaxDynamicSharedMemorySize, DS_SMEM);

    float* t_ptr;    cudaGetSymbolAddress((void**)&t_ptr, g_t);
    float* comb_ptr; cudaGetSymbolAddress((void**)&comb_ptr, g_combined);

    repack_kernel<<<OUTC, 256>>>(ds_w);
    border_kernel<<<BB, 256>>>();
    pool_kernel<<<BB*MID, 256>>>(x);
    gen_kernel<<<dim3(BB, 9), 128>>>(Wkg);
    dw_kernel<1><<<dim3(BB*MID, 2), 256, smem1>>>(x, 0, nullptr, nullptr, comb_ptr, 2*MID);
    dw_kernel<2><<<dim3(BB*MID, 2), 256, smem2>>>(x, MID, gdw_w, gdw_b, t_ptr, MID);
    pw_kernel<<<dim3(HW/128, BB), 256>>>(gpw_w, gpw_b, bn1_g, bn1_b, bn1_m, bn1_v);
    transpose_kernel<<<dim3(HH, BB), 256>>>();
    ds_mma_kernel<<<dim3(4, (BB*OHW)/128), 256, DS_SMEM>>>(
        ds_b, bn2_g, bn2_b, bn2_m, bn2_v, out);
}

// round 15
// speedup vs baseline: 1.4954x; 1.1434x over previous
#include <cuda_runtime.h>
#include <cuda_fp16.h>
#include <cstddef>
#include <cstdint>

#define BB   16
#define MID  128
#define OUTC 512
#define HH   112
#define WW   112
#define HW   (HH*WW)      // 12544
#define OH   56
#define OW   56
#define OHW  (OH*OW)      // 3136
#define EPSF 1e-5f

// ---- legacy tensor-core mma fp16 (baseline PTX, works on sm_103 non-'a') ----
__device__ __forceinline__ void mma_f16(float* c, const uint32_t* a,
                                        uint32_t b0, uint32_t b1) {
    asm volatile(
        "mma.sync.aligned.m16n8k16.row.col.f32.f16.f16.f32 "
        "{%0,%1,%2,%3}, {%4,%5,%6,%7}, {%8,%9}, {%0,%1,%2,%3};"
        : "+f"(c[0]), "+f"(c[1]), "+f"(c[2]), "+f"(c[3])
        : "r"(a[0]), "r"(a[1]), "r"(a[2]), "r"(a[3]), "r"(b0), "r"(b1));
}

#define LDMX4(r0, r1, r2, r3, addr) \
    asm volatile("ldmatrix.sync.aligned.m8n8.x4.shared.b16 {%0,%1,%2,%3}, [%4];" \
        : "=r"(r0), "=r"(r1), "=r"(r2), "=r"(r3) : "r"(addr))
#define LDMX4T(r0, r1, r2, r3, addr) \
    asm volatile("ldmatrix.sync.aligned.m8n8.x4.trans.shared.b16 {%0,%1,%2,%3}, [%4];" \
        : "=r"(r0), "=r"(r1), "=r"(r2), "=r"(r3) : "r"(addr))

__device__ __forceinline__ uint32_t smem_u32(const void* p) {
    uint32_t a;
    asm("{ .reg .u64 t; cvta.to.shared.u64 t, %1; cvt.u32.u64 %0, t; }" : "=r"(a) : "l"(p));
    return a;
}

// ---- scratch (static device globals; no allocation; 128B-aligned) ----
__device__ __align__(128) float g_pooled[BB*MID];
__device__ __align__(128) float g_gen[BB*MID*9];
__device__ __align__(128) __half g_th[(size_t)BB*MID*HW];          // dw2 out hi (NCHW)
__device__ __align__(128) __half g_tl[(size_t)BB*MID*HW];          // dw2 out lo (NCHW)
__device__ __align__(128) float g_combined[(size_t)BB*2*MID*HW];   // NCHW fp32 (local half used)
__device__ __align__(128) __half g_bhi[(size_t)BB*114*114*256];    // padded NHWC fp16 hi
__device__ __align__(128) __half g_blo[(size_t)BB*114*114*256];    // padded NHWC fp16 lo
__device__ __align__(128) __half g_wh[(size_t)9*OUTC*256];         // [tap][co][cin] fp16
__device__ __align__(128) __half g_pwh[MID*MID];                   // pw weights fp16 [co][cin]

// ============================================================
// 1) global average pool
// ============================================================
__global__ void pool_kernel(const float* __restrict__ x) {
    int bc = blockIdx.x;
    int b = bc / MID, c = bc % MID;
    const float4* p = (const float4*)(x + ((size_t)(b*2*MID + c))*HW);
    float s = 0.f;
    for (int i = threadIdx.x; i < HW/4; i += 256) {
        float4 v = p[i];
        s += v.x + v.y + v.z + v.w;
    }
    __shared__ float red[256];
    red[threadIdx.x] = s;
    __syncthreads();
    for (int o = 128; o > 0; o >>= 1) {
        if (threadIdx.x < o) red[threadIdx.x] += red[threadIdx.x + o];
        __syncthreads();
    }
    if (threadIdx.x == 0) g_pooled[bc] = red[0] * (1.f/(float)HW);
}

// ============================================================
// 2) kernel-gen
// ============================================================
__global__ void gen_kernel(const float* __restrict__ Wkg) {
    int b = blockIdx.x;
    int o = blockIdx.y * 128 + threadIdx.x;
    __shared__ float ps[MID];
    ps[threadIdx.x] = g_pooled[b*MID + threadIdx.x];
    __syncthreads();
    const float4* wr = (const float4*)(Wkg + (size_t)o*MID);
    float s = 0.f;
    #pragma unroll
    for (int i = 0; i < MID/4; i++) {
        float4 w4 = wr[i];
        s += w4.x*ps[4*i] + w4.y*ps[4*i+1] + w4.z*ps[4*i+2] + w4.w*ps[4*i+3];
    }
    g_gen[b*MID*9 + o] = fmaxf(s, 0.f);
}

// ============================================================
// 3) depthwise 3x3, half-plane per CTA; O16=1 writes fp16 hi/lo
// ============================================================
template<int DIL, int O16>
__global__ void dw_kernel(const float* __restrict__ x, int in_chan_off,
                          const float* __restrict__ kper,
                          const float* __restrict__ bias,
                          float* __restrict__ outbuf, int out_nchan) {
    constexpr int P  = DIL;
    constexpr int W2 = WW + 2*P;
    constexpr int RH = 56;
    constexpr int H2 = RH + 2*P;
    extern __shared__ float sm[];
    int bc = blockIdx.x;
    int r0 = blockIdx.y * RH;
    int b = bc / MID, c = bc % MID;
    const float* in = x + ((size_t)(b*2*MID) + in_chan_off + c)*HW;
    int tid = threadIdx.x;

    for (int i = tid; i < H2*W2; i += 256) {
        int lr = i / W2, lc = i % W2;
        int gr = r0 - P + lr, gc = lc - P;
        float v = 0.f;
        if ((unsigned)gr < HH && (unsigned)gc < WW) v = in[gr*WW + gc];
        sm[i] = v;
    }
    __syncthreads();

    float k[9];
    const float* kp = kper ? (kper + c*9) : (g_gen + (b*MID + c)*9);
    #pragma unroll
    for (int t = 0; t < 9; t++) k[t] = kp[t];
    float bv = bias ? bias[c] : 0.f;

    if (tid < 224) {
        int lr = tid >> 2, c0 = (tid & 3)*28;
        size_t oidx = ((size_t)b*(O16 ? MID : out_nchan) + c)*HW + (r0 + lr)*WW + c0;
        float* op = outbuf + ((size_t)b*out_nchan + c)*HW + (r0 + lr)*WW + c0;
        const float* base = sm + lr*W2 + c0;
        #pragma unroll 4
        for (int q = 0; q < 28; q++) {
            float s = bv;
            #pragma unroll
            for (int kh = 0; kh < 3; kh++)
                #pragma unroll
                for (int kw = 0; kw < 3; kw++)
                    s = fmaf(base[kh*DIL*W2 + kw*DIL + q], k[kh*3+kw], s);
            if (O16) {
                __half hv = __float2half_rn(s);
                g_th[oidx + q] = hv;
                g_tl[oidx + q] = __float2half_rn(s - __half2float(hv));
            } else {
                op[q] = s;
            }
        }
    }
}

// ============================================================
// 4) pw via mma fp16 2-term: 1x1 conv + bias + BN + ReLU
//    CTA: 128 co x 64 px, K=128 single-shot; NHWC hi/lo out
// ============================================================
#define PW_RSA 272
#define PW_RSB 144
#define PW_A_OFF 0
#define PW_BH_OFF 34816
#define PW_BL_OFF (34816 + 18432)
#define PW_SMEM (34816 + 2*18432)    // 71680 B
__global__ void __launch_bounds__(256, 2) pw_mma_kernel(
    const float* __restrict__ bpw,
    const float* __restrict__ bn_g, const float* __restrict__ bn_b,
    const float* __restrict__ bn_m, const float* __restrict__ bn_v) {
    extern __shared__ __align__(16) char smb[];
    uint32_t smem = smem_u32(smb);
    int tid  = threadIdx.x;
    int lane = tid & 31, w = tid >> 5;
    int wm = w & 3, wn = w >> 2;          // co group 32, px group 32
    int b  = blockIdx.y;
    int p0 = blockIdx.x * 64;

    // stage A (weights fp16, 32KB data, pad rows)
    for (int cI = tid; cI < 2048; cI += 256) {
        int row = cI >> 4, off = cI & 15;
        uint4 v = *(const uint4*)(g_pwh + row*MID + off*8);
        *(uint4*)(smb + PW_A_OFF + row*PW_RSA + off*16) = v;
    }
    // stage B hi/lo ([cin][64px], 16KB each, pad rows)
    for (int cI = tid; cI < 1024; cI += 256) {
        int row = cI >> 3, off = cI & 7;
        size_t src = ((size_t)(b*MID + row))*HW + p0 + off*8;
        *(uint4*)(smb + PW_BH_OFF + row*PW_RSB + off*16) = *(const uint4*)(g_th + src);
        *(uint4*)(smb + PW_BL_OFF + row*PW_RSB + off*16) = *(const uint4*)(g_tl + src);
    }
    __syncthreads();

    float acc[2][4][4];
    #pragma unroll
    for (int i = 0; i < 2; i++)
        #pragma unroll
        for (int j = 0; j < 4; j++)
            #pragma unroll
            for (int e = 0; e < 4; e++) acc[i][j][e] = 0.f;

    uint32_t aBase = smem + PW_A_OFF + (uint32_t)((wm*32 + (lane & 15))*PW_RSA + (lane >> 4)*16);
    uint32_t bOff  = (uint32_t)((lane & 7)*PW_RSB + ((lane >> 3) & 1)*(8*PW_RSB)
                                + ((lane >> 4) & 1)*16 + wn*64);
    #pragma unroll
    for (int ks = 0; ks < 8; ks++) {
        uint32_t bh[8], bl[8];
        uint32_t bb = bOff + ks*(16*PW_RSB);
        LDMX4T(bh[0], bh[1], bh[2], bh[3], smem + PW_BH_OFF + bb);
        LDMX4T(bh[4], bh[5], bh[6], bh[7], smem + PW_BH_OFF + bb + 32);
        LDMX4T(bl[0], bl[1], bl[2], bl[3], smem + PW_BL_OFF + bb);
        LDMX4T(bl[4], bl[5], bl[6], bl[7], smem + PW_BL_OFF + bb + 32);
        #pragma unroll
        for (int i = 0; i < 2; i++) {
            uint32_t a[4];
            LDMX4(a[0], a[1], a[2], a[3], aBase + i*(16*PW_RSA) + ks*32);
            #pragma unroll
            for (int j = 0; j < 4; j++) {
                mma_f16(acc[i][j], a, bh[2*j], bh[2*j+1]);   // w * hi
                mma_f16(acc[i][j], a, bl[2*j], bl[2*j+1]);   // w * lo
            }
        }
    }

    // epilogue: BN+ReLU, hi/lo split into smem [px64][co128], then NHWC out
    __syncthreads();
    __half* epH = (__half*)smb;            // 16384 B
    __half* epL = (__half*)(smb + 16384);  // 16384 B
    int g = lane >> 2, tig = lane & 3;
    #pragma unroll
    for (int i = 0; i < 2; i++) {
        int co0 = wm*32 + i*16 + g;
        int co1 = co0 + 8;
        float inv0 = bn_g[co0] * rsqrtf(bn_v[co0] + EPSF);
        float sh0  = bn_b[co0] - bn_m[co0]*inv0 + bpw[co0]*inv0;
        float inv1 = bn_g[co1] * rsqrtf(bn_v[co1] + EPSF);
        float sh1  = bn_b[co1] - bn_m[co1]*inv1 + bpw[co1]*inv1;
        #pragma unroll
        for (int j = 0; j < 4; j++) {
            int n0 = wn*32 + j*8 + 2*tig;
            #pragma unroll
            for (int e = 0; e < 2; e++) {
                float v0 = fmaxf(fmaf(acc[i][j][e],   inv0, sh0), 0.f);
                float v1 = fmaxf(fmaf(acc[i][j][2+e], inv1, sh1), 0.f);
                __half h0 = __float2half_rn(v0);
                __half h1 = __float2half_rn(v1);
                epH[(n0+e)*128 + co0] = h0;
                epL[(n0+e)*128 + co0] = __float2half_rn(v0 - __half2float(h0));
                epH[(n0+e)*128 + co1] = h1;
                epL[(n0+e)*128 + co1] = __float2half_rn(v1 - __half2float(h1));
            }
        }
    }
    __syncthreads();
    for (int cI = tid; cI < 1024; cI += 256) {
        int row = cI >> 4, off = cI & 15;
        int px = p0 + row;
        int h = px / WW, wq = px % WW;
        size_t dst = (((size_t)b*114 + h + 1)*114 + wq + 1)*256 + MID + off*8;
        *(uint4*)(g_bhi + dst) = *(const uint4*)(epH + row*128 + off*8);
        *(uint4*)(g_blo + dst) = *(const uint4*)(epL + row*128 + off*8);
    }
}

// ============================================================
// 5a) weight repack: dsw -> [tap][co][cin] fp16
// ============================================================
__global__ void repack_kernel(const float* __restrict__ dsw) {
    int co = blockIdx.x, cin = threadIdx.x;
    const float* src = dsw + ((size_t)co*256 + cin)*9;
    #pragma unroll
    for (int t = 0; t < 9; t++)
        g_wh[((size_t)t*OUTC + co)*256 + cin] = __float2half_rn(src[t]);
}
// 5a') pw weights fp16
__global__ void pwrep_kernel(const float* __restrict__ wpw) {
    int co = blockIdx.x, cin = threadIdx.x;
    g_pwh[co*MID + cin] = __float2half_rn(wpw[co*MID + cin]);
}

// ============================================================
// 5b) border zero for padded NHWC fp16 buffers
// ============================================================
__global__ void border_kernel() {
    size_t base = (size_t)blockIdx.x * 114*114*256;
    int tid = threadIdx.x;
    __half z = __float2half_rn(0.f);
    for (int idx = tid; idx < 114*256; idx += 256) {
        g_bhi[base + idx] = z;  g_blo[base + idx] = z;
        g_bhi[base + (size_t)113*114*256 + idx] = z;
        g_blo[base + (size_t)113*114*256 + idx] = z;
    }
    for (int idx = tid; idx < 112*256; idx += 256) {
        int h = idx >> 8, c = idx & 255;
        size_t i0 = base + ((size_t)(h+1)*114)*256 + c;
        size_t i1 = base + ((size_t)(h+1)*114 + 113)*256 + c;
        g_bhi[i0] = z; g_blo[i0] = z;
        g_bhi[i1] = z; g_blo[i1] = z;
    }
}

// ============================================================
// 5c) transpose LOCAL half: NCHW fp32 -> padded NHWC fp16 hi/lo
// ============================================================
__global__ void transpose_kernel() {
    __shared__ float t[64][113];
    int h = blockIdx.x, b = blockIdx.y;
    int tid = threadIdx.x;
    for (int c0 = 0; c0 < 128; c0 += 64) {
        for (int idx = tid; idx < 64*112; idx += 256) {
            int c = idx / 112, w = idx % 112;
            t[c][w] = g_combined[((size_t)(b*256 + c0 + c))*HW + h*WW + w];
        }
        __syncthreads();
        size_t dbase = (((size_t)b*114 + h + 1)*114 + 1)*256 + c0;
        for (int idx = tid; idx < 112*64; idx += 256) {
            int w = idx >> 6, c = idx & 63;
            float v = t[c][w];
            __half hi = __float2half_rn(v);
            float r = v - __half2float(hi);
            g_bhi[dbase + (size_t)w*256 + c] = hi;
            g_blo[dbase + (size_t)w*256 + c] = __float2half_rn(r);
        }
        __syncthreads();
    }
}

// ============================================================
// 6) downsample: mma.sync fp16 2-term implicit GEMM (R12-frozen)
// ============================================================
#define STG_W   7680
#define DS_SMEM (2*STG_W*4)
__global__ void __launch_bounds__(256, 2) ds_mma_kernel(
    const float* __restrict__ dsb,
    const float* __restrict__ bn_g, const float* __restrict__ bn_b,
    const float* __restrict__ bn_m, const float* __restrict__ bn_v,
    float* __restrict__ out) {
    extern __shared__ __align__(16) uint32_t smw[];
    uint32_t smemB = smem_u32(smw);
    int tid  = threadIdx.x;
    int lane = tid & 31, w = tid >> 5;
    int wm = w & 1, wn = w >> 1;
    int coB = blockIdx.x * 128;
    int p0  = blockIdx.y * 128;

    int r  = tid >> 1, hf = tid & 1;
    size_t aBase = (size_t)(coB + r)*256 + hf*16;
    size_t bBase;
    {
        int pg = p0 + r;
        int bimg = pg / OHW, lpx = pg % OHW;
        int ohh = lpx / OW, oww = lpx % OW;
        bBase = ((size_t)(bimg*114 + 2*ohh)*114 + 2*oww)*256 + hf*16;
    }
    uint32_t sA = (uint32_t)(r*20 + hf*8);

    uint32_t aLm = (uint32_t)((wm*64 + (lane & 15))*80 + (lane >> 4)*16);
    uint32_t bLm = (uint32_t)((wn*32 + (lane & 7) + ((lane >> 4) & 1)*8)*80
                              + ((lane >> 3) & 1)*16);

    float acc[4][4][4];
    #pragma unroll
    for (int i = 0; i < 4; i++)
        #pragma unroll
        for (int j = 0; j < 4; j++)
            #pragma unroll
            for (int e = 0; e < 4; e++) acc[i][j][e] = 0.f;

    float4 rA0, rA1, rH0, rH1, rL0, rL1;
    {
        const float4* ap = (const float4*)(g_wh + aBase);
        rA0 = ap[0]; rA1 = ap[1];
        const float4* hp = (const float4*)(g_bhi + bBase);
        rH0 = hp[0]; rH1 = hp[1];
        const float4* lp = (const float4*)(g_blo + bBase);
        rL0 = lp[0]; rL1 = lp[1];
    }

    for (int st = 0; st < 72; st++) {
        uint32_t sbW = (uint32_t)(st & 1) * STG_W;
        {
            float4* ad = (float4*)(smw + sbW + sA);
            ad[0] = rA0; ad[1] = rA1;
            float4* hd = (float4*)(smw + sbW + 2560 + sA);
            hd[0] = rH0; hd[1] = rH1;
            float4* ld = (float4*)(smw + sbW + 5120 + sA);
            ld[0] = rL0; ld[1] = rL1;
        }
        __syncthreads();
        if (st < 71) {
            int sn = st + 1;
            int tap = sn >> 3, cc = sn & 7;
            size_t ao = aBase + (size_t)tap*(OUTC*256) + cc*32;
            size_t bo = bBase + (size_t)((tap/3)*114 + tap%3)*256 + cc*32;
            const float4* ap = (const float4*)(g_wh + ao);
            rA0 = ap[0]; rA1 = ap[1];
            const float4* hp = (const float4*)(g_bhi + bo);
            rH0 = hp[0]; rH1 = hp[1];
            const float4* lp = (const float4*)(g_blo + bo);
            rL0 = lp[0]; rL1 = lp[1];
        }
        uint32_t bufA  = smemB + sbW*4;
        uint32_t bufBh = bufA + 10240;
        uint32_t bufBl = bufA + 20480;
        #pragma unroll
        for (int s2 = 0; s2 < 2; s2++) {
            uint32_t bh[8], bl[8];
            LDMX4(bh[0], bh[1], bh[2], bh[3], bufBh + bLm + s2*32);
            LDMX4(bh[4], bh[5], bh[6], bh[7], bufBh + bLm + 1280 + s2*32);
            LDMX4(bl[0], bl[1], bl[2], bl[3], bufBl + bLm + s2*32);
            LDMX4(bl[4], bl[5], bl[6], bl[7], bufBl + bLm + 1280 + s2*32);
            #pragma unroll
            for (int i = 0; i < 4; i++) {
                uint32_t a[4];
                LDMX4(a[0], a[1], a[2], a[3], bufA + aLm + i*1280 + s2*32);
                #pragma unroll
                for (int j = 0; j < 4; j++) {
                    int p2 = (j >> 1)*4 + (j & 1)*2;
                    mma_f16(acc[i][j], a, bh[p2], bh[p2+1]);
                    mma_f16(acc[i][j], a, bl[p2], bl[p2+1]);
                }
            }
        }
    }

    int g  = lane >> 2, tig = lane & 3;
    #pragma unroll
    for (int i = 0; i < 4; i++) {
        int coA = coB + wm*64 + i*16 + g;
        int coC = coA + 8;
        float invA = bn_g[coA] * rsqrtf(bn_v[coA] + EPSF);
        float shA  = bn_b[coA] - bn_m[coA]*invA + dsb[coA]*invA;
        float invC = bn_g[coC] * rsqrtf(bn_v[coC] + EPSF);
        float shC  = bn_b[coC] - bn_m[coC]*invC + dsb[coC]*invC;
        #pragma unroll
        for (int j = 0; j < 4; j++) {
            int n0 = p0 + wn*32 + j*8 + 2*tig;
            #pragma unroll
            for (int e = 0; e < 2; e++) {
                int pgx = n0 + e;
                int b = pgx / OHW, l = pgx % OHW;
                out[((size_t)(b*OUTC + coA))*OHW + l] =
                    fmaxf(fmaf(acc[i][j][e], invA, shA), 0.f);
                out[((size_t)(b*OUTC + coC))*OHW + l] =
                    fmaxf(fmaf(acc[i][j][2+e], invC, shC), 0.f);
            }
        }
    }
}

// ============================================================
extern "C" void kernel_launch(void* const* d_in, const int* in_sizes, int n_in,
                              void* d_out, int out_size) {
    const float* x     = (const float*)d_in[0];
    const float* Wkg   = (const float*)d_in[1];
    const float* gdw_w = (const float*)d_in[2];
    const float* gdw_b = (const float*)d_in[3];
    const float* gpw_w = (const float*)d_in[4];
    const float* gpw_b = (const float*)d_in[5];
    const float* bn1_g = (const float*)d_in[6];
    const float* bn1_b = (const float*)d_in[7];
    const float* bn1_m = (const float*)d_in[8];
    const float* bn1_v = (const float*)d_in[9];
    const float* ds_w  = (const float*)d_in[10];
    const float* ds_b  = (const float*)d_in[11];
    const float* bn2_g = (const float*)d_in[12];
    const float* bn2_b = (const float*)d_in[13];
    const float* bn2_m = (const float*)d_in[14];
    const float* bn2_v = (const float*)d_in[15];
    float* out = (float*)d_out;

    const int smem1 = (56+2)*(WW+2)*sizeof(float);    // 26448 B
    const int smem2 = (56+4)*(WW+4)*sizeof(float);    // 27840 B
    cudaFuncSetAttribute((const void*)dw_kernel<1,0>, cudaFuncAttributeMaxDynamicSharedMemorySize, smem1);
    cudaFuncSetAttribute((const void*)dw_kernel<2,1>, cudaFuncAttributeMaxDynamicSharedMemorySize, smem2);
    cudaFuncSetAttribute((const void*)pw_mma_kernel, cudaFuncAttributeMaxDynamicSharedMemorySize, PW_SMEM);
    cudaFuncSetAttribute((const void*)ds_mma_kernel, cudaFuncAttributeMaxDynamicSharedMemorySize, DS_SMEM);

    float* comb_ptr; cudaGetSymbolAddress((void**)&comb_ptr, g_combined);

    repack_kernel<<<OUTC, 256>>>(ds_w);
    pwrep_kernel<<<MID, MID>>>(gpw_w);
    border_kernel<<<BB, 256>>>();
    pool_kernel<<<BB*MID, 256>>>(x);
    gen_kernel<<<dim3(BB, 9), 128>>>(Wkg);
    dw_kernel<1,0><<<dim3(BB*MID, 2), 256, smem1>>>(x, 0, nullptr, nullptr, comb_ptr, 2*MID);
    dw_kernel<2,1><<<dim3(BB*MID, 2), 256, smem2>>>(x, MID, gdw_w, gdw_b, nullptr, MID);
    pw_mma_kernel<<<dim3(HW/64, BB), 256, PW_SMEM>>>(gpw_b, bn1_g, bn1_b, bn1_m, bn1_v);
    transpose_kernel<<<dim3(HH, BB), 256>>>();
    ds_mma_kernel<<<dim3(4, (BB*OHW)/128), 256, DS_SMEM>>>(
        ds_b, bn2_g, bn2_b, bn2_m, bn2_v, out);
}

// round 16
// speedup vs baseline: 1.9835x; 1.3264x over previous
#include <cuda_runtime.h>
#include <cuda_fp16.h>
#include <cstddef>
#include <cstdint>

#define BB   16
#define MID  128
#define OUTC 512
#define HH   112
#define WW   112
#define HW   (HH*WW)      // 12544
#define OH   56
#define OW   56
#define OHW  (OH*OW)      // 3136
#define EPSF 1e-5f

// ---- legacy tensor-core mma fp16 (baseline PTX, works on sm_103 non-'a') ----
__device__ __forceinline__ void mma_f16(float* c, const uint32_t* a,
                                        uint32_t b0, uint32_t b1) {
    asm volatile(
        "mma.sync.aligned.m16n8k16.row.col.f32.f16.f16.f32 "
        "{%0,%1,%2,%3}, {%4,%5,%6,%7}, {%8,%9}, {%0,%1,%2,%3};"
        : "+f"(c[0]), "+f"(c[1]), "+f"(c[2]), "+f"(c[3])
        : "r"(a[0]), "r"(a[1]), "r"(a[2]), "r"(a[3]), "r"(b0), "r"(b1));
}

#define LDMX4(r0, r1, r2, r3, addr) \
    asm volatile("ldmatrix.sync.aligned.m8n8.x4.shared.b16 {%0,%1,%2,%3}, [%4];" \
        : "=r"(r0), "=r"(r1), "=r"(r2), "=r"(r3) : "r"(addr))
#define LDMX4T(r0, r1, r2, r3, addr) \
    asm volatile("ldmatrix.sync.aligned.m8n8.x4.trans.shared.b16 {%0,%1,%2,%3}, [%4];" \
        : "=r"(r0), "=r"(r1), "=r"(r2), "=r"(r3) : "r"(addr))

__device__ __forceinline__ uint32_t smem_u32(const void* p) {
    uint32_t a;
    asm("{ .reg .u64 t; cvta.to.shared.u64 t, %1; cvt.u32.u64 %0, t; }" : "=r"(a) : "l"(p));
    return a;
}

// ---- scratch (static device globals; no allocation; 128B-aligned) ----
__device__ __align__(128) float g_pooled[BB*MID];
__device__ __align__(128) float g_gen[BB*MID*9];
__device__ __align__(128) __half g_th[(size_t)BB*MID*HW];          // dw2 out hi (NCHW)
__device__ __align__(128) __half g_tl[(size_t)BB*MID*HW];          // dw2 out lo (NCHW)
__device__ __align__(128) float g_combined[(size_t)BB*2*MID*HW];   // NCHW fp32 (local half used)
__device__ __align__(128) __half g_bhi[(size_t)BB*114*114*256];    // padded NHWC fp16
__device__ __align__(128) __half g_wh[(size_t)9*OUTC*256];         // [tap][co][cin] fp16
__device__ __align__(128) __half g_pwh[MID*MID];                   // pw weights fp16 [co][cin]

// ============================================================
// 1) global average pool
// ============================================================
__global__ void pool_kernel(const float* __restrict__ x) {
    int bc = blockIdx.x;
    int b = bc / MID, c = bc % MID;
    const float4* p = (const float4*)(x + ((size_t)(b*2*MID + c))*HW);
    float s = 0.f;
    for (int i = threadIdx.x; i < HW/4; i += 256) {
        float4 v = p[i];
        s += v.x + v.y + v.z + v.w;
    }
    __shared__ float red[256];
    red[threadIdx.x] = s;
    __syncthreads();
    for (int o = 128; o > 0; o >>= 1) {
        if (threadIdx.x < o) red[threadIdx.x] += red[threadIdx.x + o];
        __syncthreads();
    }
    if (threadIdx.x == 0) g_pooled[bc] = red[0] * (1.f/(float)HW);
}

// ============================================================
// 2) kernel-gen
// ============================================================
__global__ void gen_kernel(const float* __restrict__ Wkg) {
    int b = blockIdx.x;
    int o = blockIdx.y * 128 + threadIdx.x;
    __shared__ float ps[MID];
    ps[threadIdx.x] = g_pooled[b*MID + threadIdx.x];
    __syncthreads();
    const float4* wr = (const float4*)(Wkg + (size_t)o*MID);
    float s = 0.f;
    #pragma unroll
    for (int i = 0; i < MID/4; i++) {
        float4 w4 = wr[i];
        s += w4.x*ps[4*i] + w4.y*ps[4*i+1] + w4.z*ps[4*i+2] + w4.w*ps[4*i+3];
    }
    g_gen[b*MID*9 + o] = fmaxf(s, 0.f);
}

// ============================================================
// 3) depthwise 3x3, half-plane per CTA; O16=1 writes fp16 hi/lo
// ============================================================
template<int DIL, int O16>
__global__ void dw_kernel(const float* __restrict__ x, int in_chan_off,
                          const float* __restrict__ kper,
                          const float* __restrict__ bias,
                          float* __restrict__ outbuf, int out_nchan) {
    constexpr int P  = DIL;
    constexpr int W2 = WW + 2*P;
    constexpr int RH = 56;
    constexpr int H2 = RH + 2*P;
    extern __shared__ float sm[];
    int bc = blockIdx.x;
    int r0 = blockIdx.y * RH;
    int b = bc / MID, c = bc % MID;
    const float* in = x + ((size_t)(b*2*MID) + in_chan_off + c)*HW;
    int tid = threadIdx.x;

    for (int i = tid; i < H2*W2; i += 256) {
        int lr = i / W2, lc = i % W2;
        int gr = r0 - P + lr, gc = lc - P;
        float v = 0.f;
        if ((unsigned)gr < HH && (unsigned)gc < WW) v = in[gr*WW + gc];
        sm[i] = v;
    }
    __syncthreads();

    float k[9];
    const float* kp = kper ? (kper + c*9) : (g_gen + (b*MID + c)*9);
    #pragma unroll
    for (int t = 0; t < 9; t++) k[t] = kp[t];
    float bv = bias ? bias[c] : 0.f;

    if (tid < 224) {
        int lr = tid >> 2, c0 = (tid & 3)*28;
        size_t oidx = ((size_t)b*(O16 ? MID : out_nchan) + c)*HW + (r0 + lr)*WW + c0;
        float* op = outbuf + ((size_t)b*out_nchan + c)*HW + (r0 + lr)*WW + c0;
        const float* base = sm + lr*W2 + c0;
        #pragma unroll 4
        for (int q = 0; q < 28; q++) {
            float s = bv;
            #pragma unroll
            for (int kh = 0; kh < 3; kh++)
                #pragma unroll
                for (int kw = 0; kw < 3; kw++)
                    s = fmaf(base[kh*DIL*W2 + kw*DIL + q], k[kh*3+kw], s);
            if (O16) {
                __half hv = __float2half_rn(s);
                g_th[oidx + q] = hv;
                g_tl[oidx + q] = __float2half_rn(s - __half2float(hv));
            } else {
                op[q] = s;
            }
        }
    }
}

// ============================================================
// 4) pw via mma fp16 2-term input: 1x1 conv + bias + BN + ReLU
//    CTA: 128 co x 64 px, K=128 single-shot; NHWC hi out
// ============================================================
#define PW_RSA 272
#define PW_RSB 144
#define PW_A_OFF 0
#define PW_BH_OFF 34816
#define PW_BL_OFF (34816 + 18432)
#define PW_SMEM (34816 + 2*18432)    // 71680 B
__global__ void __launch_bounds__(256, 2) pw_mma_kernel(
    const float* __restrict__ bpw,
    const float* __restrict__ bn_g, const float* __restrict__ bn_b,
    const float* __restrict__ bn_m, const float* __restrict__ bn_v) {
    extern __shared__ __align__(16) char smb[];
    uint32_t smem = smem_u32(smb);
    int tid  = threadIdx.x;
    int lane = tid & 31, w = tid >> 5;
    int wm = w & 3, wn = w >> 2;          // co group 32, px group 32
    int b  = blockIdx.y;
    int p0 = blockIdx.x * 64;

    // stage A (weights fp16, 32KB data, pad rows)
    for (int cI = tid; cI < 2048; cI += 256) {
        int row = cI >> 4, off = cI & 15;
        uint4 v = *(const uint4*)(g_pwh + row*MID + off*8);
        *(uint4*)(smb + PW_A_OFF + row*PW_RSA + off*16) = v;
    }
    // stage B hi/lo ([cin][64px], 16KB each, pad rows)
    for (int cI = tid; cI < 1024; cI += 256) {
        int row = cI >> 3, off = cI & 7;
        size_t src = ((size_t)(b*MID + row))*HW + p0 + off*8;
        *(uint4*)(smb + PW_BH_OFF + row*PW_RSB + off*16) = *(const uint4*)(g_th + src);
        *(uint4*)(smb + PW_BL_OFF + row*PW_RSB + off*16) = *(const uint4*)(g_tl + src);
    }
    __syncthreads();

    float acc[2][4][4];
    #pragma unroll
    for (int i = 0; i < 2; i++)
        #pragma unroll
        for (int j = 0; j < 4; j++)
            #pragma unroll
            for (int e = 0; e < 4; e++) acc[i][j][e] = 0.f;

    uint32_t aBase = smem + PW_A_OFF + (uint32_t)((wm*32 + (lane & 15))*PW_RSA + (lane >> 4)*16);
    uint32_t bOff  = (uint32_t)((lane & 7)*PW_RSB + ((lane >> 3) & 1)*(8*PW_RSB)
                                + ((lane >> 4) & 1)*16 + wn*64);
    #pragma unroll
    for (int ks = 0; ks < 8; ks++) {
        uint32_t bh[8], bl[8];
        uint32_t bb = bOff + ks*(16*PW_RSB);
        LDMX4T(bh[0], bh[1], bh[2], bh[3], smem + PW_BH_OFF + bb);
        LDMX4T(bh[4], bh[5], bh[6], bh[7], smem + PW_BH_OFF + bb + 32);
        LDMX4T(bl[0], bl[1], bl[2], bl[3], smem + PW_BL_OFF + bb);
        LDMX4T(bl[4], bl[5], bl[6], bl[7], smem + PW_BL_OFF + bb + 32);
        #pragma unroll
        for (int i = 0; i < 2; i++) {
            uint32_t a[4];
            LDMX4(a[0], a[1], a[2], a[3], aBase + i*(16*PW_RSA) + ks*32);
            #pragma unroll
            for (int j = 0; j < 4; j++) {
                mma_f16(acc[i][j], a, bh[2*j], bh[2*j+1]);   // w * hi
                mma_f16(acc[i][j], a, bl[2*j], bl[2*j+1]);   // w * lo
            }
        }
    }

    // epilogue: BN+ReLU, fp16 into smem [px64][co128], then NHWC out
    __syncthreads();
    __half* epH = (__half*)smb;            // 16384 B
    int g = lane >> 2, tig = lane & 3;
    #pragma unroll
    for (int i = 0; i < 2; i++) {
        int co0 = wm*32 + i*16 + g;
        int co1 = co0 + 8;
        float inv0 = bn_g[co0] * rsqrtf(bn_v[co0] + EPSF);
        float sh0  = bn_b[co0] - bn_m[co0]*inv0 + bpw[co0]*inv0;
        float inv1 = bn_g[co1] * rsqrtf(bn_v[co1] + EPSF);
        float sh1  = bn_b[co1] - bn_m[co1]*inv1 + bpw[co1]*inv1;
        #pragma unroll
        for (int j = 0; j < 4; j++) {
            int n0 = wn*32 + j*8 + 2*tig;
            #pragma unroll
            for (int e = 0; e < 2; e++) {
                float v0 = fmaxf(fmaf(acc[i][j][e],   inv0, sh0), 0.f);
                float v1 = fmaxf(fmaf(acc[i][j][2+e], inv1, sh1), 0.f);
                epH[(n0+e)*128 + co0] = __float2half_rn(v0);
                epH[(n0+e)*128 + co1] = __float2half_rn(v1);
            }
        }
    }
    __syncthreads();
    for (int cI = tid; cI < 1024; cI += 256) {
        int row = cI >> 4, off = cI & 15;
        int px = p0 + row;
        int h = px / WW, wq = px % WW;
        size_t dst = (((size_t)b*114 + h + 1)*114 + wq + 1)*256 + MID + off*8;
        *(uint4*)(g_bhi + dst) = *(const uint4*)(epH + row*128 + off*8);
    }
}

// ============================================================
// 5a) weight repack: dsw -> [tap][co][cin] fp16
// ============================================================
__global__ void repack_kernel(const float* __restrict__ dsw) {
    int co = blockIdx.x, cin = threadIdx.x;
    const float* src = dsw + ((size_t)co*256 + cin)*9;
    #pragma unroll
    for (int t = 0; t < 9; t++)
        g_wh[((size_t)t*OUTC + co)*256 + cin] = __float2half_rn(src[t]);
}
// 5a') pw weights fp16
__global__ void pwrep_kernel(const float* __restrict__ wpw) {
    int co = blockIdx.x, cin = threadIdx.x;
    g_pwh[co*MID + cin] = __float2half_rn(wpw[co*MID + cin]);
}

// ============================================================
// 5b) border zero for padded NHWC fp16 buffer
// ============================================================
__global__ void border_kernel() {
    size_t base = (size_t)blockIdx.x * 114*114*256;
    int tid = threadIdx.x;
    __half z = __float2half_rn(0.f);
    for (int idx = tid; idx < 114*256; idx += 256) {
        g_bhi[base + idx] = z;
        g_bhi[base + (size_t)113*114*256 + idx] = z;
    }
    for (int idx = tid; idx < 112*256; idx += 256) {
        int h = idx >> 8, c = idx & 255;
        g_bhi[base + ((size_t)(h+1)*114)*256 + c] = z;
        g_bhi[base + ((size_t)(h+1)*114 + 113)*256 + c] = z;
    }
}

// ============================================================
// 5c) transpose LOCAL half: NCHW fp32 -> padded NHWC fp16
// ============================================================
__global__ void transpose_kernel() {
    __shared__ float t[64][113];
    int h = blockIdx.x, b = blockIdx.y;
    int tid = threadIdx.x;
    for (int c0 = 0; c0 < 128; c0 += 64) {
        for (int idx = tid; idx < 64*112; idx += 256) {
            int c = idx / 112, w = idx % 112;
            t[c][w] = g_combined[((size_t)(b*256 + c0 + c))*HW + h*WW + w];
        }
        __syncthreads();
        size_t dbase = (((size_t)b*114 + h + 1)*114 + 1)*256 + c0;
        for (int idx = tid; idx < 112*64; idx += 256) {
            int w = idx >> 6, c = idx & 63;
            g_bhi[dbase + (size_t)w*256 + c] = __float2half_rn(t[c][w]);
        }
        __syncthreads();
    }
}

// ============================================================
// 6) downsample: mma.sync fp16 SINGLE-term implicit GEMM
//    register-prefetch double buffer + ldmatrix fragments
//    CTA: 128 co x 128 px; 8 warps, warp tile 64x32
//    smem per stage: A / B, 128 rows x 80B each (20 KB)
// ============================================================
#define STG_W   5120                     // words per stage (2 * 2560)
#define DS_SMEM (2*STG_W*4)              // 40960 B
__global__ void __launch_bounds__(256, 2) ds_mma_kernel(
    const float* __restrict__ dsb,
    const float* __restrict__ bn_g, const float* __restrict__ bn_b,
    const float* __restrict__ bn_m, const float* __restrict__ bn_v,
    float* __restrict__ out) {
    extern __shared__ __align__(16) uint32_t smw[];
    uint32_t smemB = smem_u32(smw);
    int tid  = threadIdx.x;
    int lane = tid & 31, w = tid >> 5;
    int wm = w & 1, wn = w >> 1;
    int coB = blockIdx.x * 128;
    int p0  = blockIdx.y * 128;

    int r  = tid >> 1, hf = tid & 1;
    size_t aBase = (size_t)(coB + r)*256 + hf*16;
    size_t bBase;
    {
        int pg = p0 + r;
        int bimg = pg / OHW, lpx = pg % OHW;
        int ohh = lpx / OW, oww = lpx % OW;
        bBase = ((size_t)(bimg*114 + 2*ohh)*114 + 2*oww)*256 + hf*16;
    }
    uint32_t sA = (uint32_t)(r*20 + hf*8);

    uint32_t aLm = (uint32_t)((wm*64 + (lane & 15))*80 + (lane >> 4)*16);
    uint32_t bLm = (uint32_t)((wn*32 + (lane & 7) + ((lane >> 4) & 1)*8)*80
                              + ((lane >> 3) & 1)*16);

    float acc[4][4][4];
    #pragma unroll
    for (int i = 0; i < 4; i++)
        #pragma unroll
        for (int j = 0; j < 4; j++)
            #pragma unroll
            for (int e = 0; e < 4; e++) acc[i][j][e] = 0.f;

    float4 rA0, rA1, rH0, rH1;
    {
        const float4* ap = (const float4*)(g_wh + aBase);
        rA0 = ap[0]; rA1 = ap[1];
        const float4* hp = (const float4*)(g_bhi + bBase);
        rH0 = hp[0]; rH1 = hp[1];
    }

    for (int st = 0; st < 72; st++) {
        uint32_t sbW = (uint32_t)(st & 1) * STG_W;
        {
            float4* ad = (float4*)(smw + sbW + sA);
            ad[0] = rA0; ad[1] = rA1;
            float4* hd = (float4*)(smw + sbW + 2560 + sA);
            hd[0] = rH0; hd[1] = rH1;
        }
        __syncthreads();
        if (st < 71) {
            int sn = st + 1;
            int tap = sn >> 3, cc = sn & 7;
            size_t ao = aBase + (size_t)tap*(OUTC*256) + cc*32;
            size_t bo = bBase + (size_t)((tap/3)*114 + tap%3)*256 + cc*32;
            const float4* ap = (const float4*)(g_wh + ao);
            rA0 = ap[0]; rA1 = ap[1];
            const float4* hp = (const float4*)(g_bhi + bo);
            rH0 = hp[0]; rH1 = hp[1];
        }
        uint32_t bufA  = smemB + sbW*4;
        uint32_t bufBh = bufA + 10240;
        #pragma unroll
        for (int s2 = 0; s2 < 2; s2++) {
            uint32_t bh[8];
            LDMX4(bh[0], bh[1], bh[2], bh[3], bufBh + bLm + s2*32);
            LDMX4(bh[4], bh[5], bh[6], bh[7], bufBh + bLm + 1280 + s2*32);
            #pragma unroll
            for (int i = 0; i < 4; i++) {
                uint32_t a[4];
                LDMX4(a[0], a[1], a[2], a[3], bufA + aLm + i*1280 + s2*32);
                #pragma unroll
                for (int j = 0; j < 4; j++) {
                    int p2 = (j >> 1)*4 + (j & 1)*2;
                    mma_f16(acc[i][j], a, bh[p2], bh[p2+1]);
                }
            }
        }
    }

    int g  = lane >> 2, tig = lane & 3;
    #pragma unroll
    for (int i = 0; i < 4; i++) {
        int coA = coB + wm*64 + i*16 + g;
        int coC = coA + 8;
        float invA = bn_g[coA] * rsqrtf(bn_v[coA] + EPSF);
        float shA  = bn_b[coA] - bn_m[coA]*invA + dsb[coA]*invA;
        float invC = bn_g[coC] * rsqrtf(bn_v[coC] + EPSF);
        float shC  = bn_b[coC] - bn_m[coC]*invC + dsb[coC]*invC;
        #pragma unroll
        for (int j = 0; j < 4; j++) {
            int n0 = p0 + wn*32 + j*8 + 2*tig;
            #pragma unroll
            for (int e = 0; e < 2; e++) {
                int pgx = n0 + e;
                int b = pgx / OHW, l = pgx % OHW;
                out[((size_t)(b*OUTC + coA))*OHW + l] =
                    fmaxf(fmaf(acc[i][j][e], invA, shA), 0.f);
                out[((size_t)(b*OUTC + coC))*OHW + l] =
                    fmaxf(fmaf(acc[i][j][2+e], invC, shC), 0.f);
            }
        }
    }
}

// ============================================================
extern "C" void kernel_launch(void* const* d_in, const int* in_sizes, int n_in,
                              void* d_out, int out_size) {
    const float* x     = (const float*)d_in[0];
    const float* Wkg   = (const float*)d_in[1];
    const float* gdw_w = (const float*)d_in[2];
    const float* gdw_b = (const float*)d_in[3];
    const float* gpw_w = (const float*)d_in[4];
    const float* gpw_b = (const float*)d_in[5];
    const float* bn1_g = (const float*)d_in[6];
    const float* bn1_b = (const float*)d_in[7];
    const float* bn1_m = (const float*)d_in[8];
    const float* bn1_v = (const float*)d_in[9];
    const float* ds_w  = (const float*)d_in[10];
    const float* ds_b  = (const float*)d_in[11];
    const float* bn2_g = (const float*)d_in[12];
    const float* bn2_b = (const float*)d_in[13];
    const float* bn2_m = (const float*)d_in[14];
    const float* bn2_v = (const float*)d_in[15];
    float* out = (float*)d_out;

    const int smem1 = (56+2)*(WW+2)*sizeof(float);    // 26448 B
    const int smem2 = (56+4)*(WW+4)*sizeof(float);    // 27840 B
    cudaFuncSetAttribute((const void*)dw_kernel<1,0>, cudaFuncAttributeMaxDynamicSharedMemorySize, smem1);
    cudaFuncSetAttribute((const void*)dw_kernel<2,1>, cudaFuncAttributeMaxDynamicSharedMemorySize, smem2);
    cudaFuncSetAttribute((const void*)pw_mma_kernel, cudaFuncAttributeMaxDynamicSharedMemorySize, PW_SMEM);
    cudaFuncSetAttribute((const void*)ds_mma_kernel, cudaFuncAttributeMaxDynamicSharedMemorySize, DS_SMEM);

    float* comb_ptr; cudaGetSymbolAddress((void**)&comb_ptr, g_combined);

    repack_kernel<<<OUTC, 256>>>(ds_w);
    pwrep_kernel<<<MID, MID>>>(gpw_w);
    border_kernel<<<BB, 256>>>();
    pool_kernel<<<BB*MID, 256>>>(x);
    gen_kernel<<<dim3(BB, 9), 128>>>(Wkg);
    dw_kernel<1,0><<<dim3(BB*MID, 2), 256, smem1>>>(x, 0, nullptr, nullptr, comb_ptr, 2*MID);
    dw_kernel<2,1><<<dim3(BB*MID, 2), 256, smem2>>>(x, MID, gdw_w, gdw_b, nullptr, MID);
    pw_mma_kernel<<<dim3(HW/64, BB), 256, PW_SMEM>>>(gpw_b, bn1_g, bn1_b, bn1_m, bn1_v);
    transpose_kernel<<<dim3(HH, BB), 256>>>();
    ds_mma_kernel<<<dim3(4, (BB*OHW)/128), 256, DS_SMEM>>>(
        ds_b, bn2_g, bn2_b, bn2_m, bn2_v, out);
}

// round 17
// speedup vs baseline: 2.1161x; 1.0668x over previous
#include <cuda_runtime.h>
#include <cuda_fp16.h>
#include <cstddef>
#include <cstdint>

#define BB   16
#define MID  128
#define OUTC 512
#define HH   112
#define WW   112
#define HW   (HH*WW)      // 12544
#define OH   56
#define OW   56
#define OHW  (OH*OW)      // 3136
#define EPSF 1e-5f

// ---- legacy tensor-core mma fp16 (baseline PTX, works on sm_103 non-'a') ----
__device__ __forceinline__ void mma_f16(float* c, const uint32_t* a,
                                        uint32_t b0, uint32_t b1) {
    asm volatile(
        "mma.sync.aligned.m16n8k16.row.col.f32.f16.f16.f32 "
        "{%0,%1,%2,%3}, {%4,%5,%6,%7}, {%8,%9}, {%0,%1,%2,%3};"
        : "+f"(c[0]), "+f"(c[1]), "+f"(c[2]), "+f"(c[3])
        : "r"(a[0]), "r"(a[1]), "r"(a[2]), "r"(a[3]), "r"(b0), "r"(b1));
}

#define LDMX4(r0, r1, r2, r3, addr) \
    asm volatile("ldmatrix.sync.aligned.m8n8.x4.shared.b16 {%0,%1,%2,%3}, [%4];" \
        : "=r"(r0), "=r"(r1), "=r"(r2), "=r"(r3) : "r"(addr))
#define LDMX4T(r0, r1, r2, r3, addr) \
    asm volatile("ldmatrix.sync.aligned.m8n8.x4.trans.shared.b16 {%0,%1,%2,%3}, [%4];" \
        : "=r"(r0), "=r"(r1), "=r"(r2), "=r"(r3) : "r"(addr))

__device__ __forceinline__ uint32_t smem_u32(const void* p) {
    uint32_t a;
    asm("{ .reg .u64 t; cvta.to.shared.u64 t, %1; cvt.u32.u64 %0, t; }" : "=r"(a) : "l"(p));
    return a;
}

// ---- scratch (static device globals; no allocation; 128B-aligned) ----
__device__ __align__(128) float g_pooled[BB*MID];
__device__ __align__(128) float g_gen[BB*MID*9];
__device__ __align__(128) __half g_th[(size_t)BB*MID*HW];          // dw2 out fp16 (NCHW)
__device__ __align__(128) float g_combined[(size_t)BB*2*MID*HW];   // NCHW fp32 (local half used)
__device__ __align__(128) __half g_bhi[(size_t)BB*114*114*256];    // padded NHWC fp16
__device__ __align__(128) __half g_wh[(size_t)9*OUTC*256];         // [tap][co][cin] fp16
__device__ __align__(128) __half g_pwh[MID*MID];                   // pw weights fp16 [co][cin]

// ============================================================
// 1) global average pool
// ============================================================
__global__ void pool_kernel(const float* __restrict__ x) {
    int bc = blockIdx.x;
    int b = bc / MID, c = bc % MID;
    const float4* p = (const float4*)(x + ((size_t)(b*2*MID + c))*HW);
    float s = 0.f;
    for (int i = threadIdx.x; i < HW/4; i += 256) {
        float4 v = p[i];
        s += v.x + v.y + v.z + v.w;
    }
    __shared__ float red[256];
    red[threadIdx.x] = s;
    __syncthreads();
    for (int o = 128; o > 0; o >>= 1) {
        if (threadIdx.x < o) red[threadIdx.x] += red[threadIdx.x + o];
        __syncthreads();
    }
    if (threadIdx.x == 0) g_pooled[bc] = red[0] * (1.f/(float)HW);
}

// ============================================================
// 2) kernel-gen
// ============================================================
__global__ void gen_kernel(const float* __restrict__ Wkg) {
    int b = blockIdx.x;
    int o = blockIdx.y * 128 + threadIdx.x;
    __shared__ float ps[MID];
    ps[threadIdx.x] = g_pooled[b*MID + threadIdx.x];
    __syncthreads();
    const float4* wr = (const float4*)(Wkg + (size_t)o*MID);
    float s = 0.f;
    #pragma unroll
    for (int i = 0; i < MID/4; i++) {
        float4 w4 = wr[i];
        s += w4.x*ps[4*i] + w4.y*ps[4*i+1] + w4.z*ps[4*i+2] + w4.w*ps[4*i+3];
    }
    g_gen[b*MID*9 + o] = fmaxf(s, 0.f);
}

// ============================================================
// 3) depthwise 3x3, half-plane per CTA; O16=1 writes fp16 (hi only)
// ============================================================
template<int DIL, int O16>
__global__ void dw_kernel(const float* __restrict__ x, int in_chan_off,
                          const float* __restrict__ kper,
                          const float* __restrict__ bias,
                          float* __restrict__ outbuf, int out_nchan) {
    constexpr int P  = DIL;
    constexpr int W2 = WW + 2*P;
    constexpr int RH = 56;
    constexpr int H2 = RH + 2*P;
    extern __shared__ float sm[];
    int bc = blockIdx.x;
    int r0 = blockIdx.y * RH;
    int b = bc / MID, c = bc % MID;
    const float* in = x + ((size_t)(b*2*MID) + in_chan_off + c)*HW;
    int tid = threadIdx.x;

    for (int i = tid; i < H2*W2; i += 256) {
        int lr = i / W2, lc = i % W2;
        int gr = r0 - P + lr, gc = lc - P;
        float v = 0.f;
        if ((unsigned)gr < HH && (unsigned)gc < WW) v = in[gr*WW + gc];
        sm[i] = v;
    }
    __syncthreads();

    float k[9];
    const float* kp = kper ? (kper + c*9) : (g_gen + (b*MID + c)*9);
    #pragma unroll
    for (int t = 0; t < 9; t++) k[t] = kp[t];
    float bv = bias ? bias[c] : 0.f;

    if (tid < 224) {
        int lr = tid >> 2, c0 = (tid & 3)*28;
        size_t oidx = ((size_t)b*(O16 ? MID : out_nchan) + c)*HW + (r0 + lr)*WW + c0;
        float* op = outbuf + ((size_t)b*out_nchan + c)*HW + (r0 + lr)*WW + c0;
        const float* base = sm + lr*W2 + c0;
        #pragma unroll 4
        for (int q = 0; q < 28; q++) {
            float s = bv;
            #pragma unroll
            for (int kh = 0; kh < 3; kh++)
                #pragma unroll
                for (int kw = 0; kw < 3; kw++)
                    s = fmaf(base[kh*DIL*W2 + kw*DIL + q], k[kh*3+kw], s);
            if (O16) {
                g_th[oidx + q] = __float2half_rn(s);
            } else {
                op[q] = s;
            }
        }
    }
}

// ============================================================
// 4) pw via mma fp16 single-term: 1x1 conv + bias + BN + ReLU
//    CTA: 128 co x 64 px, K=128 single-shot; NHWC fp16 out
// ============================================================
#define PW_RSA 272
#define PW_RSB 144
#define PW_A_OFF 0
#define PW_BH_OFF 34816
#define PW_SMEM (34816 + 18432)    // 53248 B
__global__ void __launch_bounds__(256, 2) pw_mma_kernel(
    const float* __restrict__ bpw,
    const float* __restrict__ bn_g, const float* __restrict__ bn_b,
    const float* __restrict__ bn_m, const float* __restrict__ bn_v) {
    extern __shared__ __align__(16) char smb[];
    uint32_t smem = smem_u32(smb);
    int tid  = threadIdx.x;
    int lane = tid & 31, w = tid >> 5;
    int wm = w & 3, wn = w >> 2;          // co group 32, px group 32
    int b  = blockIdx.y;
    int p0 = blockIdx.x * 64;

    // stage A (weights fp16, 32KB data, pad rows)
    for (int cI = tid; cI < 2048; cI += 256) {
        int row = cI >> 4, off = cI & 15;
        uint4 v = *(const uint4*)(g_pwh + row*MID + off*8);
        *(uint4*)(smb + PW_A_OFF + row*PW_RSA + off*16) = v;
    }
    // stage B ([cin][64px], 16KB, pad rows)
    for (int cI = tid; cI < 1024; cI += 256) {
        int row = cI >> 3, off = cI & 7;
        size_t src = ((size_t)(b*MID + row))*HW + p0 + off*8;
        *(uint4*)(smb + PW_BH_OFF + row*PW_RSB + off*16) = *(const uint4*)(g_th + src);
    }
    __syncthreads();

    float acc[2][4][4];
    #pragma unroll
    for (int i = 0; i < 2; i++)
        #pragma unroll
        for (int j = 0; j < 4; j++)
            #pragma unroll
            for (int e = 0; e < 4; e++) acc[i][j][e] = 0.f;

    uint32_t aBase = smem + PW_A_OFF + (uint32_t)((wm*32 + (lane & 15))*PW_RSA + (lane >> 4)*16);
    uint32_t bOff  = (uint32_t)((lane & 7)*PW_RSB + ((lane >> 3) & 1)*(8*PW_RSB)
                                + ((lane >> 4) & 1)*16 + wn*64);
    #pragma unroll
    for (int ks = 0; ks < 8; ks++) {
        uint32_t bh[8];
        uint32_t bb = bOff + ks*(16*PW_RSB);
        LDMX4T(bh[0], bh[1], bh[2], bh[3], smem + PW_BH_OFF + bb);
        LDMX4T(bh[4], bh[5], bh[6], bh[7], smem + PW_BH_OFF + bb + 32);
        #pragma unroll
        for (int i = 0; i < 2; i++) {
            uint32_t a[4];
            LDMX4(a[0], a[1], a[2], a[3], aBase + i*(16*PW_RSA) + ks*32);
            #pragma unroll
            for (int j = 0; j < 4; j++)
                mma_f16(acc[i][j], a, bh[2*j], bh[2*j+1]);
        }
    }

    // epilogue: BN+ReLU, fp16 into smem [px64][co128], then NHWC out
    __syncthreads();
    __half* epH = (__half*)smb;            // 16384 B
    int g = lane >> 2, tig = lane & 3;
    #pragma unroll
    for (int i = 0; i < 2; i++) {
        int co0 = wm*32 + i*16 + g;
        int co1 = co0 + 8;
        float inv0 = bn_g[co0] * rsqrtf(bn_v[co0] + EPSF);
        float sh0  = bn_b[co0] - bn_m[co0]*inv0 + bpw[co0]*inv0;
        float inv1 = bn_g[co1] * rsqrtf(bn_v[co1] + EPSF);
        float sh1  = bn_b[co1] - bn_m[co1]*inv1 + bpw[co1]*inv1;
        #pragma unroll
        for (int j = 0; j < 4; j++) {
            int n0 = wn*32 + j*8 + 2*tig;
            #pragma unroll
            for (int e = 0; e < 2; e++) {
                float v0 = fmaxf(fmaf(acc[i][j][e],   inv0, sh0), 0.f);
                float v1 = fmaxf(fmaf(acc[i][j][2+e], inv1, sh1), 0.f);
                epH[(n0+e)*128 + co0] = __float2half_rn(v0);
                epH[(n0+e)*128 + co1] = __float2half_rn(v1);
            }
        }
    }
    __syncthreads();
    for (int cI = tid; cI < 1024; cI += 256) {
        int row = cI >> 4, off = cI & 15;
        int px = p0 + row;
        int h = px / WW, wq = px % WW;
        size_t dst = (((size_t)b*114 + h + 1)*114 + wq + 1)*256 + MID + off*8;
        *(uint4*)(g_bhi + dst) = *(const uint4*)(epH + row*128 + off*8);
    }
}

// ============================================================
// 5a) weight repack: dsw -> [tap][co][cin] fp16
// ============================================================
__global__ void repack_kernel(const float* __restrict__ dsw) {
    int co = blockIdx.x, cin = threadIdx.x;
    const float* src = dsw + ((size_t)co*256 + cin)*9;
    #pragma unroll
    for (int t = 0; t < 9; t++)
        g_wh[((size_t)t*OUTC + co)*256 + cin] = __float2half_rn(src[t]);
}
// 5a') pw weights fp16
__global__ void pwrep_kernel(const float* __restrict__ wpw) {
    int co = blockIdx.x, cin = threadIdx.x;
    g_pwh[co*MID + cin] = __float2half_rn(wpw[co*MID + cin]);
}

// ============================================================
// 5b) border zero for padded NHWC fp16 buffer
// ============================================================
__global__ void border_kernel() {
    size_t base = (size_t)blockIdx.x * 114*114*256;
    int tid = threadIdx.x;
    __half z = __float2half_rn(0.f);
    for (int idx = tid; idx < 114*256; idx += 256) {
        g_bhi[base + idx] = z;
        g_bhi[base + (size_t)113*114*256 + idx] = z;
    }
    for (int idx = tid; idx < 112*256; idx += 256) {
        int h = idx >> 8, c = idx & 255;
        g_bhi[base + ((size_t)(h+1)*114)*256 + c] = z;
        g_bhi[base + ((size_t)(h+1)*114 + 113)*256 + c] = z;
    }
}

// ============================================================
// 5c) transpose LOCAL half: NCHW fp32 -> padded NHWC fp16
// ============================================================
__global__ void transpose_kernel() {
    __shared__ float t[64][113];
    int h = blockIdx.x, b = blockIdx.y;
    int tid = threadIdx.x;
    for (int c0 = 0; c0 < 128; c0 += 64) {
        for (int idx = tid; idx < 64*112; idx += 256) {
            int c = idx / 112, w = idx % 112;
            t[c][w] = g_combined[((size_t)(b*256 + c0 + c))*HW + h*WW + w];
        }
        __syncthreads();
        size_t dbase = (((size_t)b*114 + h + 1)*114 + 1)*256 + c0;
        for (int idx = tid; idx < 112*64; idx += 256) {
            int w = idx >> 6, c = idx & 63;
            g_bhi[dbase + (size_t)w*256 + c] = __float2half_rn(t[c][w]);
        }
        __syncthreads();
    }
}

// ============================================================
// 6) downsample: mma.sync fp16 single-term implicit GEMM (R16-frozen)
//    register-prefetch double buffer + ldmatrix fragments
//    CTA: 128 co x 128 px; 8 warps, warp tile 64x32
// ============================================================
#define STG_W   5120                     // words per stage (2 * 2560)
#define DS_SMEM (2*STG_W*4)              // 40960 B
__global__ void __launch_bounds__(256, 2) ds_mma_kernel(
    const float* __restrict__ dsb,
    const float* __restrict__ bn_g, const float* __restrict__ bn_b,
    const float* __restrict__ bn_m, const float* __restrict__ bn_v,
    float* __restrict__ out) {
    extern __shared__ __align__(16) uint32_t smw[];
    uint32_t smemB = smem_u32(smw);
    int tid  = threadIdx.x;
    int lane = tid & 31, w = tid >> 5;
    int wm = w & 1, wn = w >> 1;
    int coB = blockIdx.x * 128;
    int p0  = blockIdx.y * 128;

    int r  = tid >> 1, hf = tid & 1;
    size_t aBase = (size_t)(coB + r)*256 + hf*16;
    size_t bBase;
    {
        int pg = p0 + r;
        int bimg = pg / OHW, lpx = pg % OHW;
        int ohh = lpx / OW, oww = lpx % OW;
        bBase = ((size_t)(bimg*114 + 2*ohh)*114 + 2*oww)*256 + hf*16;
    }
    uint32_t sA = (uint32_t)(r*20 + hf*8);

    uint32_t aLm = (uint32_t)((wm*64 + (lane & 15))*80 + (lane >> 4)*16);
    uint32_t bLm = (uint32_t)((wn*32 + (lane & 7) + ((lane >> 4) & 1)*8)*80
                              + ((lane >> 3) & 1)*16);

    float acc[4][4][4];
    #pragma unroll
    for (int i = 0; i < 4; i++)
        #pragma unroll
        for (int j = 0; j < 4; j++)
            #pragma unroll
            for (int e = 0; e < 4; e++) acc[i][j][e] = 0.f;

    float4 rA0, rA1, rH0, rH1;
    {
        const float4* ap = (const float4*)(g_wh + aBase);
        rA0 = ap[0]; rA1 = ap[1];
        const float4* hp = (const float4*)(g_bhi + bBase);
        rH0 = hp[0]; rH1 = hp[1];
    }

    for (int st = 0; st < 72; st++) {
        uint32_t sbW = (uint32_t)(st & 1) * STG_W;
        {
            float4* ad = (float4*)(smw + sbW + sA);
            ad[0] = rA0; ad[1] = rA1;
            float4* hd = (float4*)(smw + sbW + 2560 + sA);
            hd[0] = rH0; hd[1] = rH1;
        }
        __syncthreads();
        if (st < 71) {
            int sn = st + 1;
            int tap = sn >> 3, cc = sn & 7;
            size_t ao = aBase + (size_t)tap*(OUTC*256) + cc*32;
            size_t bo = bBase + (size_t)((tap/3)*114 + tap%3)*256 + cc*32;
            const float4* ap = (const float4*)(g_wh + ao);
            rA0 = ap[0]; rA1 = ap[1];
            const float4* hp = (const float4*)(g_bhi + bo);
            rH0 = hp[0]; rH1 = hp[1];
        }
        uint32_t bufA  = smemB + sbW*4;
        uint32_t bufBh = bufA + 10240;
        #pragma unroll
        for (int s2 = 0; s2 < 2; s2++) {
            uint32_t bh[8];
            LDMX4(bh[0], bh[1], bh[2], bh[3], bufBh + bLm + s2*32);
            LDMX4(bh[4], bh[5], bh[6], bh[7], bufBh + bLm + 1280 + s2*32);
            #pragma unroll
            for (int i = 0; i < 4; i++) {
                uint32_t a[4];
                LDMX4(a[0], a[1], a[2], a[3], bufA + aLm + i*1280 + s2*32);
                #pragma unroll
                for (int j = 0; j < 4; j++) {
                    int p2 = (j >> 1)*4 + (j & 1)*2;
                    mma_f16(acc[i][j], a, bh[p2], bh[p2+1]);
                }
            }
        }
    }

    int g  = lane >> 2, tig = lane & 3;
    #pragma unroll
    for (int i = 0; i < 4; i++) {
        int coA = coB + wm*64 + i*16 + g;
        int coC = coA + 8;
        float invA = bn_g[coA] * rsqrtf(bn_v[coA] + EPSF);
        float shA  = bn_b[coA] - bn_m[coA]*invA + dsb[coA]*invA;
        float invC = bn_g[coC] * rsqrtf(bn_v[coC] + EPSF);
        float shC  = bn_b[coC] - bn_m[coC]*invC + dsb[coC]*invC;
        #pragma unroll
        for (int j = 0; j < 4; j++) {
            int n0 = p0 + wn*32 + j*8 + 2*tig;
            #pragma unroll
            for (int e = 0; e < 2; e++) {
                int pgx = n0 + e;
                int b = pgx / OHW, l = pgx % OHW;
                out[((size_t)(b*OUTC + coA))*OHW + l] =
                    fmaxf(fmaf(acc[i][j][e], invA, shA), 0.f);
                out[((size_t)(b*OUTC + coC))*OHW + l] =
                    fmaxf(fmaf(acc[i][j][2+e], invC, shC), 0.f);
            }
        }
    }
}

// ============================================================
extern "C" void kernel_launch(void* const* d_in, const int* in_sizes, int n_in,
                              void* d_out, int out_size) {
    const float* x     = (const float*)d_in[0];
    const float* Wkg   = (const float*)d_in[1];
    const float* gdw_w = (const float*)d_in[2];
    const float* gdw_b = (const float*)d_in[3];
    const float* gpw_w = (const float*)d_in[4];
    const float* gpw_b = (const float*)d_in[5];
    const float* bn1_g = (const float*)d_in[6];
    const float* bn1_b = (const float*)d_in[7];
    const float* bn1_m = (const float*)d_in[8];
    const float* bn1_v = (const float*)d_in[9];
    const float* ds_w  = (const float*)d_in[10];
    const float* ds_b  = (const float*)d_in[11];
    const float* bn2_g = (const float*)d_in[12];
    const float* bn2_b = (const float*)d_in[13];
    const float* bn2_m = (const float*)d_in[14];
    const float* bn2_v = (const float*)d_in[15];
    float* out = (float*)d_out;

    const int smem1 = (56+2)*(WW+2)*sizeof(float);    // 26448 B
    const int smem2 = (56+4)*(WW+4)*sizeof(float);    // 27840 B
    cudaFuncSetAttribute((const void*)dw_kernel<1,0>, cudaFuncAttributeMaxDynamicSharedMemorySize, smem1);
    cudaFuncSetAttribute((const void*)dw_kernel<2,1>, cudaFuncAttributeMaxDynamicSharedMemorySize, smem2);
    cudaFuncSetAttribute((const void*)pw_mma_kernel, cudaFuncAttributeMaxDynamicSharedMemorySize, PW_SMEM);
    cudaFuncSetAttribute((const void*)ds_mma_kernel, cudaFuncAttributeMaxDynamicSharedMemorySize, DS_SMEM);

    float* comb_ptr; cudaGetSymbolAddress((void**)&comb_ptr, g_combined);

    repack_kernel<<<OUTC, 256>>>(ds_w);
    pwrep_kernel<<<MID, MID>>>(gpw_w);
    border_kernel<<<BB, 256>>>();
    pool_kernel<<<BB*MID, 256>>>(x);
    gen_kernel<<<dim3(BB, 9), 128>>>(Wkg);
    dw_kernel<1,0><<<dim3(BB*MID, 2), 256, smem1>>>(x, 0, nullptr, nullptr, comb_ptr, 2*MID);
    dw_kernel<2,1><<<dim3(BB*MID, 2), 256, smem2>>>(x, MID, gdw_w, gdw_b, nullptr, MID);
    pw_mma_kernel<<<dim3(HW/64, BB), 256, PW_SMEM>>>(gpw_b, bn1_g, bn1_b, bn1_m, bn1_v);
    transpose_kernel<<<dim3(HH, BB), 256>>>();
    ds_mma_kernel<<<dim3(4, (BB*OHW)/128), 256, DS_SMEM>>>(
        ds_b, bn2_g, bn2_b, bn2_m, bn2_v, out);
}